// round 13
// baseline (speedup 1.0000x reference)
#include <cuda_runtime.h>
#include <cstdint>

// Problem constants
constexpr int NN  = 50000;   // nodes
constexpr int NE  = 800000;  // edges
constexpr int ND  = 64;      // node dim
constexpr int ED  = 64;      // edge dim
constexpr int HID = 128;     // hidden

constexpr int NTILES = NE / 128;            // 6250 edge tiles
constexpr int NTILN  = (NN + 127) / 128;    // 391 node tiles
constexpr int PGRID  = 296;                 // 2 CTAs x 148 SMs, persistent

// Scratch (device globals: allocation-free)
__device__ float g_PR[NN * HID];   // x @ eW1[64:128]   (fp32 exact)
__device__ float g_PC[NN * HID];   // x @ eW1[128:192]  (fp32 exact)
__device__ float g_PX[NN * HID];   // x @ nW1[0:64]     (fp32 exact)
__device__ float g_msg[NN * ED];   // scatter-add accumulator

// ---------------------------------------------------------------------------
// helpers
// ---------------------------------------------------------------------------
__device__ __forceinline__ uint32_t f32_to_tf32(float f) {
    uint32_t u;
    asm("cvt.rna.tf32.f32 %0, %1;" : "=r"(u) : "f"(f));
    return u;
}

__device__ __forceinline__ void mma_tf32(float d[4], const uint32_t a[4],
                                         const uint32_t b[2]) {
    asm volatile(
        "mma.sync.aligned.m16n8k8.row.col.f32.tf32.tf32.f32 "
        "{%0,%1,%2,%3}, {%4,%5,%6,%7}, {%8,%9}, {%0,%1,%2,%3};"
        : "+f"(d[0]), "+f"(d[1]), "+f"(d[2]), "+f"(d[3])
        : "r"(a[0]), "r"(a[1]), "r"(a[2]), "r"(a[3]), "r"(b[0]), "r"(b[1]));
}

__device__ __forceinline__ uint32_t smem_u32(const void* p) {
    uint32_t a;
    asm("{ .reg .u64 t; cvta.to.shared.u64 t, %1; cvt.u32.u64 %0, t; }"
        : "=r"(a) : "l"(p));
    return a;
}

#define CP_ASYNC16(dst_u32, src_ptr) \
    asm volatile("cp.async.cg.shared.global [%0], [%1], 16;" \
                 :: "r"(dst_u32), "l"(src_ptr))
#define CP_ASYNC16_Z(dst_u32, src_ptr, src_bytes) \
    asm volatile("cp.async.cg.shared.global [%0], [%1], 16, %2;" \
                 :: "r"(dst_u32), "l"(src_ptr), "r"(src_bytes))
#define CP_COMMIT()  asm volatile("cp.async.commit_group;")
#define CP_WAIT0()   asm volatile("cp.async.wait_group 0;" ::: "memory")

// ---------------------------------------------------------------------------
__global__ void zero_msg_kernel() {
    int i = blockIdx.x * blockDim.x + threadIdx.x;
    reinterpret_cast<float4*>(g_msg)[i] = make_float4(0.f, 0.f, 0.f, 0.f);
}

// ---------------------------------------------------------------------------
// Precompute PR/PC (fp32 exact): GEMM [NN,64] @ [64,256]
// ---------------------------------------------------------------------------
__global__ void __launch_bounds__(256, 2) precompute_kernel(
    const float* __restrict__ x, const float* __restrict__ eW1)
{
    extern __shared__ float sm[];
    float* Xs = sm;               // [64][68]
    float* Ws = sm + 64 * 68;     // [64][256]

    const int n0 = blockIdx.x * 64;
    const int tid = threadIdx.x;

    for (int idx = tid; idx < 64 * 64; idx += 256) {
        int r = idx >> 6, c = idx & 63;
        int n = n0 + r;
        Xs[r * 68 + c] = (n < NN) ? x[n * 64 + c] : 0.f;
    }
    for (int idx = tid; idx < 64 * 256; idx += 256) {
        int k = idx >> 8, j = idx & 255;
        float v = (j < 128) ? eW1[(64 + k) * 128 + j]
                            : eW1[(128 + k) * 128 + (j - 128)];
        Ws[k * 256 + j] = v;
    }
    __syncthreads();

    const int tx = tid & 15;
    const int ty = tid >> 4;

    float acc[4][16];
    #pragma unroll
    for (int i = 0; i < 4; i++)
        #pragma unroll
        for (int j = 0; j < 16; j++) acc[i][j] = 0.f;

    #pragma unroll 4
    for (int k = 0; k < 64; k++) {
        float a[4];
        #pragma unroll
        for (int i = 0; i < 4; i++) a[i] = Xs[(ty * 4 + i) * 68 + k];
        const float4 b0 = *(const float4*)&Ws[k * 256 + tx * 16 + 0];
        const float4 b1 = *(const float4*)&Ws[k * 256 + tx * 16 + 4];
        const float4 b2 = *(const float4*)&Ws[k * 256 + tx * 16 + 8];
        const float4 b3 = *(const float4*)&Ws[k * 256 + tx * 16 + 12];
        float b[16] = {b0.x, b0.y, b0.z, b0.w, b1.x, b1.y, b1.z, b1.w,
                       b2.x, b2.y, b2.z, b2.w, b3.x, b3.y, b3.z, b3.w};
        #pragma unroll
        for (int i = 0; i < 4; i++)
            #pragma unroll
            for (int j = 0; j < 16; j++)
                acc[i][j] = fmaf(a[i], b[j], acc[i][j]);
    }

    float* dst = (tx < 8) ? g_PR : g_PC;
    int    cb  = (tx < 8) ? tx * 16 : (tx - 8) * 16;
    #pragma unroll
    for (int i = 0; i < 4; i++) {
        int n = n0 + ty * 4 + i;
        if (n >= NN) continue;
        #pragma unroll
        for (int j = 0; j < 16; j += 4) {
            float4 o = make_float4(acc[i][j], acc[i][j + 1],
                                   acc[i][j + 2], acc[i][j + 3]);
            *(float4*)&dst[n * 128 + cb + j] = o;
        }
    }
}

// ---------------------------------------------------------------------------
// Precompute PX (fp32 exact): PX = x @ nW1[0:64]   [NN,128]
// ---------------------------------------------------------------------------
__global__ void __launch_bounds__(256, 2) precompute_px_kernel(
    const float* __restrict__ x, const float* __restrict__ nW1)
{
    extern __shared__ float sm[];
    float* Xs = sm;               // [64][68]
    float* Ws = sm + 64 * 68;     // [64][128]

    const int n0 = blockIdx.x * 64;
    const int tid = threadIdx.x;

    for (int idx = tid; idx < 64 * 64; idx += 256) {
        int r = idx >> 6, c = idx & 63;
        int n = n0 + r;
        Xs[r * 68 + c] = (n < NN) ? x[n * 64 + c] : 0.f;
    }
    for (int idx = tid; idx < 64 * 128; idx += 256)
        Ws[idx] = nW1[idx];
    __syncthreads();

    const int tx = tid & 15;
    const int ty = tid >> 4;

    float acc[4][8];
    #pragma unroll
    for (int i = 0; i < 4; i++)
        #pragma unroll
        for (int j = 0; j < 8; j++) acc[i][j] = 0.f;

    #pragma unroll 4
    for (int k = 0; k < 64; k++) {
        float a[4];
        #pragma unroll
        for (int i = 0; i < 4; i++) a[i] = Xs[(ty * 4 + i) * 68 + k];
        const float4 b0 = *(const float4*)&Ws[k * 128 + tx * 8 + 0];
        const float4 b1 = *(const float4*)&Ws[k * 128 + tx * 8 + 4];
        float b[8] = {b0.x, b0.y, b0.z, b0.w, b1.x, b1.y, b1.z, b1.w};
        #pragma unroll
        for (int i = 0; i < 4; i++)
            #pragma unroll
            for (int j = 0; j < 8; j++)
                acc[i][j] = fmaf(a[i], b[j], acc[i][j]);
    }

    #pragma unroll
    for (int i = 0; i < 4; i++) {
        int n = n0 + ty * 4 + i;
        if (n >= NN) continue;
        *(float4*)&g_PX[n * 128 + tx * 8 + 0] =
            make_float4(acc[i][0], acc[i][1], acc[i][2], acc[i][3]);
        *(float4*)&g_PX[n * 128 + tx * 8 + 4] =
            make_float4(acc[i][4], acc[i][5], acc[i][6], acc[i][7]);
    }
}

// ---------------------------------------------------------------------------
// Smem layout for persistent mma kernels (103168 B, 2 CTAs/SM)
// ---------------------------------------------------------------------------
constexpr int S_A   = 0;          // A [128][68] row-major (raw fp32)
constexpr int S_B1  = 8704;       // B1frag [pane=kk*16+nn][66]
constexpr int S_B2  = 17152;      // B2frag [pane=kk*8+nn][66]
constexpr int S_EB1 = 25600;      // bias1 [128]
constexpr int S_EB2 = 25728;      // bias2 [64]
constexpr int MMA_SMEM_BYTES = 25792 * 4;   // 103168

// ---------------------------------------------------------------------------
// Edge kernel — persistent, barrier-free main loop, per-warp A slabs,
// float4 + quad-shuffle gathers (64B/row wavefronts, PR+PC pre-summed).
// ---------------------------------------------------------------------------
__global__ void __launch_bounds__(256, 2) edge_kernel(
    const float* __restrict__ edge_attr,
    const int*   __restrict__ edge_index,   // [2][NE]
    const float* __restrict__ eW1,
    const float* __restrict__ eb1,
    const float* __restrict__ eW2,
    const float* __restrict__ eb2,
    float* __restrict__ out_edge)
{
    extern __shared__ float sm[];
    uint32_t* smu = reinterpret_cast<uint32_t*>(sm);
    const uint32_t sbase = smem_u32(sm);

    const int tid  = threadIdx.x;
    const int lane = tid & 31;
    const int w    = tid >> 5;
    const int gr   = lane >> 2;
    const int ct   = lane & 3;
    const int s0   = ct >> 1;
    const int s1   = 2 + (ct >> 1);
    const int sel  = ct & 1;
    const int even = (ct & 1) == 0;
    const int qb   = 4 * (ct >> 1);
    const int r1   = 16 * w + gr;
    const int r2   = r1 + 8;

    const uint32_t slabBase = sbase + (S_A + 16 * w * 68) * 4;

    // ---- prologue: B fragments + biases (block-cooperative, once) ----
    for (int t = tid; t < 2048; t += 256) {
        int k = t >> 5, n4 = (t & 31) << 2;
        float4 v = *(const float4*)&eW1[k * 128 + n4];
        int pane = (k >> 3) * 16 + (n4 >> 3);
        int j    = (k >> 2) & 1;
        int ln0  = ((n4 & 7) << 2) | (k & 3);
        uint32_t* p = &smu[S_B1 + pane * 66 + j];
        p[(ln0 + 0)  * 2] = f32_to_tf32(v.x);
        p[(ln0 + 4)  * 2] = f32_to_tf32(v.y);
        p[(ln0 + 8)  * 2] = f32_to_tf32(v.z);
        p[(ln0 + 12) * 2] = f32_to_tf32(v.w);
    }
    for (int t = tid; t < 2048; t += 256) {
        int k = t >> 4, n4 = (t & 15) << 2;
        float4 v = *(const float4*)&eW2[k * 64 + n4];
        int pane = (k >> 3) * 8 + (n4 >> 3);
        int j    = (k >> 2) & 1;
        int ln0  = ((n4 & 7) << 2) | (k & 3);
        uint32_t* p = &smu[S_B2 + pane * 66 + j];
        p[(ln0 + 0)  * 2] = f32_to_tf32(v.x);
        p[(ln0 + 4)  * 2] = f32_to_tf32(v.y);
        p[(ln0 + 8)  * 2] = f32_to_tf32(v.z);
        p[(ln0 + 12) * 2] = f32_to_tf32(v.w);
    }
    if (tid < 128) sm[S_EB1 + tid] = eb1[tid];
    if (tid < 64)  sm[S_EB2 + tid] = eb2[tid];

    // ---- per-warp A slab for first tile ----
    {
        int e0 = blockIdx.x * 128;
        #pragma unroll
        for (int i = 0; i < 8; i++) {
            int idx = lane + 32 * i;
            int rl = idx >> 4, c4 = (idx & 15) << 2;
            CP_ASYNC16(slabBase + (rl * 68 + c4) * 4,
                       edge_attr + (size_t)(e0 + 16 * w + rl) * 64 + c4);
        }
        CP_COMMIT();
    }
    __syncthreads();   // B fragments visible; the ONLY block barrier
    CP_WAIT0();
    __syncwarp();

    // ---- persistent tile loop (no block barriers) ----
    for (int tile = blockIdx.x; tile < NTILES; tile += PGRID) {
        const int e0 = tile * 128;

        const int re1 = __ldg(&edge_index[e0 + r1]);
        const int re2 = __ldg(&edge_index[e0 + r2]);
        const int ce1 = __ldg(&edge_index[NE + e0 + r1]);
        const int ce2 = __ldg(&edge_index[NE + e0 + r2]);

        // layer-1 mma (A from own slab, conflict-free scalar LDS)
        float acc[16][4];
        #pragma unroll
        for (int nn = 0; nn < 16; nn++) {
            acc[nn][0] = acc[nn][1] = acc[nn][2] = acc[nn][3] = 0.f;
        }
        #pragma unroll
        for (int kk = 0; kk < 8; kk++) {
            const int col = kk * 8 + ct;
            uint32_t a[4];
            a[0] = smu[S_A + r1 * 68 + col];
            a[1] = smu[S_A + r2 * 68 + col];
            a[2] = smu[S_A + r1 * 68 + col + 4];
            a[3] = smu[S_A + r2 * 68 + col + 4];
            #pragma unroll
            for (int nn = 0; nn < 16; nn++) {
                uint32_t b[2];
                const uint2 bv = *(const uint2*)&smu[S_B1 + (kk * 16 + nn) * 66 + lane * 2];
                b[0] = bv.x; b[1] = bv.y;
                mma_tf32(acc[nn], a, b);
            }
        }
        __syncwarp();   // all lanes done reading this warp's slab

        // per-warp prefetch of next tile's slab
        {
            int ntile = tile + PGRID;
            if (ntile < NTILES) {
                int ne0 = ntile * 128;
                #pragma unroll
                for (int i = 0; i < 8; i++) {
                    int idx = lane + 32 * i;
                    int rl = idx >> 4, c4 = (idx & 15) << 2;
                    CP_ASYNC16(slabBase + (rl * 68 + c4) * 4,
                               edge_attr + (size_t)(ne0 + 16 * w + rl) * 64 + c4);
                }
            }
            CP_COMMIT();
        }

        // ---- epilogue: float4 gathers (64B/row spans) + quad-shuffle ----
        // H = rna(relu(C1 + (PR+PC) + eb1))
        {
            const float* PR1 = g_PR + (size_t)re1 * 128;
            const float* PR2 = g_PR + (size_t)re2 * 128;
            const float* PC1 = g_PC + (size_t)ce1 * 128;
            const float* PC2 = g_PC + (size_t)ce2 * 128;
            #pragma unroll
            for (int j = 0; j < 8; j++) {
                const int off = 16 * j + 4 * ct;
                float4 va1 = *(const float4*)&PR1[off];
                float4 vb1 = *(const float4*)&PC1[off];
                float4 va2 = *(const float4*)&PR2[off];
                float4 vb2 = *(const float4*)&PC2[off];
                // pre-sum (identical redistribution targets)
                float4 gA = make_float4(va1.x + vb1.x, va1.y + vb1.y,
                                        va1.z + vb1.z, va1.w + vb1.w);
                float4 gB = make_float4(va2.x + vb2.x, va2.y + vb2.y,
                                        va2.z + vb2.z, va2.w + vb2.w);
                // redistribute gA (row r1 terms)
                float At0 = __shfl_sync(0xffffffffu, gA.x, s0, 4);
                float At1 = __shfl_sync(0xffffffffu, gA.y, s0, 4);
                float At2 = __shfl_sync(0xffffffffu, gA.z, s0, 4);
                float At3 = __shfl_sync(0xffffffffu, gA.w, s0, 4);
                float Au0 = __shfl_sync(0xffffffffu, gA.x, s1, 4);
                float Au1 = __shfl_sync(0xffffffffu, gA.y, s1, 4);
                float Au2 = __shfl_sync(0xffffffffu, gA.z, s1, 4);
                float Au3 = __shfl_sync(0xffffffffu, gA.w, s1, 4);
                float G1n0x = sel ? At2 : At0, G1n0y = sel ? At3 : At1;
                float G1n1x = sel ? Au2 : Au0, G1n1y = sel ? Au3 : Au1;
                // redistribute gB (row r2 terms)
                float Bt0 = __shfl_sync(0xffffffffu, gB.x, s0, 4);
                float Bt1 = __shfl_sync(0xffffffffu, gB.y, s0, 4);
                float Bt2 = __shfl_sync(0xffffffffu, gB.z, s0, 4);
                float Bt3 = __shfl_sync(0xffffffffu, gB.w, s0, 4);
                float Bu0 = __shfl_sync(0xffffffffu, gB.x, s1, 4);
                float Bu1 = __shfl_sync(0xffffffffu, gB.y, s1, 4);
                float Bu2 = __shfl_sync(0xffffffffu, gB.z, s1, 4);
                float Bu3 = __shfl_sync(0xffffffffu, gB.w, s1, 4);
                float G2n0x = sel ? Bt2 : Bt0, G2n0y = sel ? Bt3 : Bt1;
                float G2n1x = sel ? Bu2 : Bu0, G2n1y = sel ? Bu3 : Bu1;

                const int nn0 = 2 * j, nn1 = 2 * j + 1;
                float2 bb0 = *(const float2*)&sm[S_EB1 + nn0 * 8 + 2 * ct];
                float2 bb1 = *(const float2*)&sm[S_EB1 + nn1 * 8 + 2 * ct];
                acc[nn0][0] = __uint_as_float(f32_to_tf32(fmaxf(acc[nn0][0] + G1n0x + bb0.x, 0.f)));
                acc[nn0][1] = __uint_as_float(f32_to_tf32(fmaxf(acc[nn0][1] + G1n0y + bb0.y, 0.f)));
                acc[nn0][2] = __uint_as_float(f32_to_tf32(fmaxf(acc[nn0][2] + G2n0x + bb0.x, 0.f)));
                acc[nn0][3] = __uint_as_float(f32_to_tf32(fmaxf(acc[nn0][3] + G2n0y + bb0.y, 0.f)));
                acc[nn1][0] = __uint_as_float(f32_to_tf32(fmaxf(acc[nn1][0] + G1n1x + bb1.x, 0.f)));
                acc[nn1][1] = __uint_as_float(f32_to_tf32(fmaxf(acc[nn1][1] + G1n1y + bb1.y, 0.f)));
                acc[nn1][2] = __uint_as_float(f32_to_tf32(fmaxf(acc[nn1][2] + G2n1x + bb1.x, 0.f)));
                acc[nn1][3] = __uint_as_float(f32_to_tf32(fmaxf(acc[nn1][3] + G2n1y + bb1.y, 0.f)));
            }
        }

        // quad-shuffle transpose -> layer-2 A fragments
        #pragma unroll
        for (int kk = 0; kk < 16; kk++) {
            float t0 = __shfl_sync(0xffffffffu, acc[kk][0], s0, 4);
            float t1 = __shfl_sync(0xffffffffu, acc[kk][1], s0, 4);
            float t2 = __shfl_sync(0xffffffffu, acc[kk][2], s0, 4);
            float t3 = __shfl_sync(0xffffffffu, acc[kk][3], s0, 4);
            float u0 = __shfl_sync(0xffffffffu, acc[kk][0], s1, 4);
            float u1 = __shfl_sync(0xffffffffu, acc[kk][1], s1, 4);
            float u2 = __shfl_sync(0xffffffffu, acc[kk][2], s1, 4);
            float u3 = __shfl_sync(0xffffffffu, acc[kk][3], s1, 4);
            acc[kk][0] = sel ? t1 : t0;
            acc[kk][1] = sel ? t3 : t2;
            acc[kk][2] = sel ? u1 : u0;
            acc[kk][3] = sel ? u3 : u2;
        }

        // layer-2 mma
        float acc2[8][4];
        #pragma unroll
        for (int nn = 0; nn < 8; nn++) {
            acc2[nn][0] = acc2[nn][1] = acc2[nn][2] = acc2[nn][3] = 0.f;
        }
        #pragma unroll
        for (int kk = 0; kk < 16; kk++) {
            uint32_t a[4];
            a[0] = __float_as_uint(acc[kk][0]);
            a[1] = __float_as_uint(acc[kk][1]);
            a[2] = __float_as_uint(acc[kk][2]);
            a[3] = __float_as_uint(acc[kk][3]);
            #pragma unroll
            for (int nn = 0; nn < 8; nn++) {
                uint32_t b[2];
                const uint2 bv = *(const uint2*)&smu[S_B2 + (kk * 8 + nn) * 66 + lane * 2];
                b[0] = bv.x; b[1] = bv.y;
                mma_tf32(acc2[nn], a, b);
            }
        }

        // output: lane-pair exchange -> float4 stores + red.v4
        {
            const int row  = even ? r1 : r2;
            const int ced  = even ? ce1 : ce2;
            float* op = out_edge + (size_t)(e0 + row) * 64;
            float* mp = g_msg + (size_t)ced * 64;
            #pragma unroll
            for (int nn = 0; nn < 8; nn++) {
                float sa = __shfl_xor_sync(0xffffffffu, acc2[nn][0], 1);
                float sb = __shfl_xor_sync(0xffffffffu, acc2[nn][1], 1);
                float sc = __shfl_xor_sync(0xffffffffu, acc2[nn][2], 1);
                float sd = __shfl_xor_sync(0xffffffffu, acc2[nn][3], 1);
                int base = nn * 8 + qb;
                float4 bb = *(const float4*)&sm[S_EB2 + base];
                float4 o;
                if (even) {
                    o = make_float4(acc2[nn][0] + bb.x, acc2[nn][1] + bb.y,
                                    sa + bb.z, sb + bb.w);
                } else {
                    o = make_float4(sc + bb.x, sd + bb.y,
                                    acc2[nn][2] + bb.z, acc2[nn][3] + bb.w);
                }
                *(float4*)(op + base) = o;
                asm volatile("red.global.add.v4.f32 [%0], {%1,%2,%3,%4};"
                             :: "l"(mp + base), "f"(o.x), "f"(o.y), "f"(o.z), "f"(o.w)
                             : "memory");
            }
        }

        CP_WAIT0();
        __syncwarp();
    }
}

// ---------------------------------------------------------------------------
// Node kernel — same skeleton; PX gather via float4 + quad-shuffle.
// ---------------------------------------------------------------------------
__global__ void __launch_bounds__(256, 2) node_kernel(
    const float* __restrict__ nW1, const float* __restrict__ nb1,
    const float* __restrict__ nW2, const float* __restrict__ nb2,
    float* __restrict__ out_node)
{
    extern __shared__ float sm[];
    uint32_t* smu = reinterpret_cast<uint32_t*>(sm);
    const uint32_t sbase = smem_u32(sm);

    const int tid  = threadIdx.x;
    const int lane = tid & 31;
    const int w    = tid >> 5;
    const int gr   = lane >> 2;
    const int ct   = lane & 3;
    const int s0   = ct >> 1;
    const int s1   = 2 + (ct >> 1);
    const int sel  = ct & 1;
    const int even = (ct & 1) == 0;
    const int qb   = 4 * (ct >> 1);
    const int r1   = 16 * w + gr;
    const int r2   = r1 + 8;

    const uint32_t slabBase = sbase + (S_A + 16 * w * 68) * 4;

    // ---- prologue ----
    for (int t = tid; t < 2048; t += 256) {
        int k = t >> 5, n4 = (t & 31) << 2;
        float4 v = *(const float4*)&nW1[(64 + k) * 128 + n4];
        int pane = (k >> 3) * 16 + (n4 >> 3);
        int j    = (k >> 2) & 1;
        int ln0  = ((n4 & 7) << 2) | (k & 3);
        uint32_t* p = &smu[S_B1 + pane * 66 + j];
        p[(ln0 + 0)  * 2] = f32_to_tf32(v.x);
        p[(ln0 + 4)  * 2] = f32_to_tf32(v.y);
        p[(ln0 + 8)  * 2] = f32_to_tf32(v.z);
        p[(ln0 + 12) * 2] = f32_to_tf32(v.w);
    }
    for (int t = tid; t < 2048; t += 256) {
        int k = t >> 4, n4 = (t & 15) << 2;
        float4 v = *(const float4*)&nW2[k * 64 + n4];
        int pane = (k >> 3) * 8 + (n4 >> 3);
        int j    = (k >> 2) & 1;
        int ln0  = ((n4 & 7) << 2) | (k & 3);
        uint32_t* p = &smu[S_B2 + pane * 66 + j];
        p[(ln0 + 0)  * 2] = f32_to_tf32(v.x);
        p[(ln0 + 4)  * 2] = f32_to_tf32(v.y);
        p[(ln0 + 8)  * 2] = f32_to_tf32(v.z);
        p[(ln0 + 12) * 2] = f32_to_tf32(v.w);
    }
    if (tid < 128) sm[S_EB1 + tid] = nb1[tid];
    if (tid < 64)  sm[S_EB2 + tid] = nb2[tid];

    {
        int n0 = blockIdx.x * 128;
        #pragma unroll
        for (int i = 0; i < 8; i++) {
            int idx = lane + 32 * i;
            int rl = idx >> 4, c4 = (idx & 15) << 2;
            int row = n0 + 16 * w + rl;
            uint32_t nbytes = (row < NN) ? 16u : 0u;
            const float* src = g_msg + (size_t)min(row, NN - 1) * 64 + c4;
            CP_ASYNC16_Z(slabBase + (rl * 68 + c4) * 4, src, nbytes);
        }
        CP_COMMIT();
    }
    __syncthreads();
    CP_WAIT0();
    __syncwarp();

    for (int tile = blockIdx.x; tile < NTILN; tile += PGRID) {
        const int n0 = tile * 128;

        float acc[16][4];
        #pragma unroll
        for (int nn = 0; nn < 16; nn++) {
            acc[nn][0] = acc[nn][1] = acc[nn][2] = acc[nn][3] = 0.f;
        }
        #pragma unroll
        for (int kk = 0; kk < 8; kk++) {
            const int col = kk * 8 + ct;
            uint32_t a[4];
            a[0] = smu[S_A + r1 * 68 + col];
            a[1] = smu[S_A + r2 * 68 + col];
            a[2] = smu[S_A + r1 * 68 + col + 4];
            a[3] = smu[S_A + r2 * 68 + col + 4];
            #pragma unroll
            for (int nn = 0; nn < 16; nn++) {
                uint32_t b[2];
                const uint2 bv = *(const uint2*)&smu[S_B1 + (kk * 16 + nn) * 66 + lane * 2];
                b[0] = bv.x; b[1] = bv.y;
                mma_tf32(acc[nn], a, b);
            }
        }
        __syncwarp();

        {
            int ntile = tile + PGRID;
            if (ntile < NTILN) {
                int nn0 = ntile * 128;
                #pragma unroll
                for (int i = 0; i < 8; i++) {
                    int idx = lane + 32 * i;
                    int rl = idx >> 4, c4 = (idx & 15) << 2;
                    int row = nn0 + 16 * w + rl;
                    uint32_t nbytes = (row < NN) ? 16u : 0u;
                    const float* src = g_msg + (size_t)min(row, NN - 1) * 64 + c4;
                    CP_ASYNC16_Z(slabBase + (rl * 68 + c4) * 4, src, nbytes);
                }
            }
            CP_COMMIT();
        }

        // epilogue: float4 + quad-shuffle PX gathers
        {
            const float* PX1 = g_PX + (size_t)min(n0 + r1, NN - 1) * 128;
            const float* PX2 = g_PX + (size_t)min(n0 + r2, NN - 1) * 128;
            #pragma unroll
            for (int j = 0; j < 8; j++) {
                const int off = 16 * j + 4 * ct;
                float4 gA = *(const float4*)&PX1[off];
                float4 gB = *(const float4*)&PX2[off];
                float At0 = __shfl_sync(0xffffffffu, gA.x, s0, 4);
                float At1 = __shfl_sync(0xffffffffu, gA.y, s0, 4);
                float At2 = __shfl_sync(0xffffffffu, gA.z, s0, 4);
                float At3 = __shfl_sync(0xffffffffu, gA.w, s0, 4);
                float Au0 = __shfl_sync(0xffffffffu, gA.x, s1, 4);
                float Au1 = __shfl_sync(0xffffffffu, gA.y, s1, 4);
                float Au2 = __shfl_sync(0xffffffffu, gA.z, s1, 4);
                float Au3 = __shfl_sync(0xffffffffu, gA.w, s1, 4);
                float G1n0x = sel ? At2 : At0, G1n0y = sel ? At3 : At1;
                float G1n1x = sel ? Au2 : Au0, G1n1y = sel ? Au3 : Au1;
                float Bt0 = __shfl_sync(0xffffffffu, gB.x, s0, 4);
                float Bt1 = __shfl_sync(0xffffffffu, gB.y, s0, 4);
                float Bt2 = __shfl_sync(0xffffffffu, gB.z, s0, 4);
                float Bt3 = __shfl_sync(0xffffffffu, gB.w, s0, 4);
                float Bu0 = __shfl_sync(0xffffffffu, gB.x, s1, 4);
                float Bu1 = __shfl_sync(0xffffffffu, gB.y, s1, 4);
                float Bu2 = __shfl_sync(0xffffffffu, gB.z, s1, 4);
                float Bu3 = __shfl_sync(0xffffffffu, gB.w, s1, 4);
                float G2n0x = sel ? Bt2 : Bt0, G2n0y = sel ? Bt3 : Bt1;
                float G2n1x = sel ? Bu2 : Bu0, G2n1y = sel ? Bu3 : Bu1;

                const int nn0 = 2 * j, nn1 = 2 * j + 1;
                float2 bb0 = *(const float2*)&sm[S_EB1 + nn0 * 8 + 2 * ct];
                float2 bb1 = *(const float2*)&sm[S_EB1 + nn1 * 8 + 2 * ct];
                acc[nn0][0] = __uint_as_float(f32_to_tf32(fmaxf(acc[nn0][0] + G1n0x + bb0.x, 0.f)));
                acc[nn0][1] = __uint_as_float(f32_to_tf32(fmaxf(acc[nn0][1] + G1n0y + bb0.y, 0.f)));
                acc[nn0][2] = __uint_as_float(f32_to_tf32(fmaxf(acc[nn0][2] + G2n0x + bb0.x, 0.f)));
                acc[nn0][3] = __uint_as_float(f32_to_tf32(fmaxf(acc[nn0][3] + G2n0y + bb0.y, 0.f)));
                acc[nn1][0] = __uint_as_float(f32_to_tf32(fmaxf(acc[nn1][0] + G1n1x + bb1.x, 0.f)));
                acc[nn1][1] = __uint_as_float(f32_to_tf32(fmaxf(acc[nn1][1] + G1n1y + bb1.y, 0.f)));
                acc[nn1][2] = __uint_as_float(f32_to_tf32(fmaxf(acc[nn1][2] + G2n1x + bb1.x, 0.f)));
                acc[nn1][3] = __uint_as_float(f32_to_tf32(fmaxf(acc[nn1][3] + G2n1y + bb1.y, 0.f)));
            }
        }

        #pragma unroll
        for (int kk = 0; kk < 16; kk++) {
            float t0 = __shfl_sync(0xffffffffu, acc[kk][0], s0, 4);
            float t1 = __shfl_sync(0xffffffffu, acc[kk][1], s0, 4);
            float t2 = __shfl_sync(0xffffffffu, acc[kk][2], s0, 4);
            float t3 = __shfl_sync(0xffffffffu, acc[kk][3], s0, 4);
            float u0 = __shfl_sync(0xffffffffu, acc[kk][0], s1, 4);
            float u1 = __shfl_sync(0xffffffffu, acc[kk][1], s1, 4);
            float u2 = __shfl_sync(0xffffffffu, acc[kk][2], s1, 4);
            float u3 = __shfl_sync(0xffffffffu, acc[kk][3], s1, 4);
            acc[kk][0] = sel ? t1 : t0;
            acc[kk][1] = sel ? t3 : t2;
            acc[kk][2] = sel ? u1 : u0;
            acc[kk][3] = sel ? u3 : u2;
        }

        float acc2[8][4];
        #pragma unroll
        for (int nn = 0; nn < 8; nn++) {
            acc2[nn][0] = acc2[nn][1] = acc2[nn][2] = acc2[nn][3] = 0.f;
        }
        #pragma unroll
        for (int kk = 0; kk < 16; kk++) {
            uint32_t a[4];
            a[0] = __float_as_uint(acc[kk][0]);
            a[1] = __float_as_uint(acc[kk][1]);
            a[2] = __float_as_uint(acc[kk][2]);
            a[3] = __float_as_uint(acc[kk][3]);
            #pragma unroll
            for (int nn = 0; nn < 8; nn++) {
                uint32_t b[2];
                const uint2 bv = *(const uint2*)&smu[S_B2 + (kk * 8 + nn) * 66 + lane * 2];
                b[0] = bv.x; b[1] = bv.y;
                mma_tf32(acc2[nn], a, b);
            }
        }

        {
            const int row = even ? r1 : r2;
            const int n   = n0 + row;
            float* op = out_node + (size_t)n * 64;
            #pragma unroll
            for (int nn = 0; nn < 8; nn++) {
                float sa = __shfl_xor_sync(0xffffffffu, acc2[nn][0], 1);
                float sb = __shfl_xor_sync(0xffffffffu, acc2[nn][1], 1);
                float sc = __shfl_xor_sync(0xffffffffu, acc2[nn][2], 1);
                float sd = __shfl_xor_sync(0xffffffffu, acc2[nn][3], 1);
                int base = nn * 8 + qb;
                float4 bb = *(const float4*)&sm[S_EB2 + base];
                float4 o;
                if (even) {
                    o = make_float4(acc2[nn][0] + bb.x, acc2[nn][1] + bb.y,
                                    sa + bb.z, sb + bb.w);
                } else {
                    o = make_float4(sc + bb.x, sd + bb.y,
                                    acc2[nn][2] + bb.z, acc2[nn][3] + bb.w);
                }
                if (n < NN) *(float4*)(op + base) = o;
            }
        }

        CP_WAIT0();
        __syncwarp();
    }
}

// ---------------------------------------------------------------------------
extern "C" void kernel_launch(void* const* d_in, const int* in_sizes, int n_in,
                              void* d_out, int out_size)
{
    const float* x    = (const float*)d_in[0];
    const int*   ei   = (const int*)  d_in[1];
    const float* ea   = (const float*)d_in[2];
    const float* eW1  = (const float*)d_in[3];
    const float* eb1  = (const float*)d_in[4];
    const float* eW2  = (const float*)d_in[5];
    const float* eb2  = (const float*)d_in[6];
    const float* nW1  = (const float*)d_in[7];
    const float* nb1  = (const float*)d_in[8];
    const float* nW2  = (const float*)d_in[9];
    const float* nb2  = (const float*)d_in[10];

    float* out_node = (float*)d_out;             // [NN, 64]
    float* out_edge = (float*)d_out + NN * ND;   // [NE, 64]

    const int smem_pre = (64 * 68 + 64 * 256) * 4;   // 82944
    const int smem_px  = (64 * 68 + 64 * 128) * 4;   // 50176

    cudaFuncSetAttribute(precompute_kernel,
        cudaFuncAttributeMaxDynamicSharedMemorySize, smem_pre);
    cudaFuncSetAttribute(precompute_px_kernel,
        cudaFuncAttributeMaxDynamicSharedMemorySize, smem_px);
    cudaFuncSetAttribute(edge_kernel,
        cudaFuncAttributeMaxDynamicSharedMemorySize, MMA_SMEM_BYTES);
    cudaFuncSetAttribute(node_kernel,
        cudaFuncAttributeMaxDynamicSharedMemorySize, MMA_SMEM_BYTES);

    zero_msg_kernel<<<(NN * ED / 4) / 256, 256>>>();
    precompute_kernel<<<(NN + 63) / 64, 256, smem_pre>>>(x, eW1);
    precompute_px_kernel<<<(NN + 63) / 64, 256, smem_px>>>(x, nW1);
    edge_kernel<<<PGRID, 256, MMA_SMEM_BYTES>>>(ea, ei, eW1, eb1, eW2, eb2, out_edge);
    node_kernel<<<PGRID, 256, MMA_SMEM_BYTES>>>(nW1, nb1, nW2, nb2, out_node);
}

// round 14
// speedup vs baseline: 1.0279x; 1.0279x over previous
#include <cuda_runtime.h>
#include <cstdint>

// Problem constants
constexpr int NN  = 50000;   // nodes
constexpr int NE  = 800000;  // edges
constexpr int ND  = 64;      // node dim
constexpr int ED  = 64;      // edge dim
constexpr int HID = 128;     // hidden

constexpr int NTILES = NE / 128;            // 6250 edge tiles
constexpr int NTILN  = (NN + 127) / 128;    // 391 node tiles
constexpr int PGRID  = 296;                 // 2 CTAs x 148 SMs, persistent

// Scratch (device globals: allocation-free)
// NOTE: PR/PC/PX are stored with the hidden dim PERMUTED by p(m) and with
// eb1 (resp. nb1) pre-folded into PR (resp. PX).
__device__ float g_PR[NN * HID];   // perm(x @ eW1[64:128] + eb1)
__device__ float g_PC[NN * HID];   // perm(x @ eW1[128:192])
__device__ float g_PX[NN * HID];   // perm(x @ nW1[0:64] + nb1)
__device__ float g_msg[NN * ED];   // scatter-add accumulator

// hidden-unit permutation: maps mma position m -> physical table offset
__host__ __device__ __forceinline__ int hperm(int m) {
    return 16 * (m >> 4) + 4 * ((m >> 1) & 3) + 2 * ((m >> 3) & 1) + (m & 1);
}

// ---------------------------------------------------------------------------
// helpers
// ---------------------------------------------------------------------------
__device__ __forceinline__ uint32_t f32_to_tf32(float f) {
    uint32_t u;
    asm("cvt.rna.tf32.f32 %0, %1;" : "=r"(u) : "f"(f));
    return u;
}

__device__ __forceinline__ void mma_tf32(float d[4], const uint32_t a[4],
                                         const uint32_t b[2]) {
    asm volatile(
        "mma.sync.aligned.m16n8k8.row.col.f32.tf32.tf32.f32 "
        "{%0,%1,%2,%3}, {%4,%5,%6,%7}, {%8,%9}, {%0,%1,%2,%3};"
        : "+f"(d[0]), "+f"(d[1]), "+f"(d[2]), "+f"(d[3])
        : "r"(a[0]), "r"(a[1]), "r"(a[2]), "r"(a[3]), "r"(b[0]), "r"(b[1]));
}

__device__ __forceinline__ uint32_t smem_u32(const void* p) {
    uint32_t a;
    asm("{ .reg .u64 t; cvta.to.shared.u64 t, %1; cvt.u32.u64 %0, t; }"
        : "=r"(a) : "l"(p));
    return a;
}

#define CP_ASYNC16(dst_u32, src_ptr) \
    asm volatile("cp.async.cg.shared.global [%0], [%1], 16;" \
                 :: "r"(dst_u32), "l"(src_ptr))
#define CP_ASYNC16_Z(dst_u32, src_ptr, src_bytes) \
    asm volatile("cp.async.cg.shared.global [%0], [%1], 16, %2;" \
                 :: "r"(dst_u32), "l"(src_ptr), "r"(src_bytes))
#define CP_COMMIT()  asm volatile("cp.async.commit_group;")
#define CP_WAIT0()   asm volatile("cp.async.wait_group 0;" ::: "memory")

#define RELU_RNA(x) __uint_as_float(f32_to_tf32(fmaxf((x), 0.f)))

// ---------------------------------------------------------------------------
__global__ void zero_msg_kernel() {
    int i = blockIdx.x * blockDim.x + threadIdx.x;
    reinterpret_cast<float4*>(g_msg)[i] = make_float4(0.f, 0.f, 0.f, 0.f);
}

// ---------------------------------------------------------------------------
// Precompute PR/PC (fp32 exact, permuted cols, eb1 folded into PR):
// GEMM [NN,64] @ [64,256]
// ---------------------------------------------------------------------------
__global__ void __launch_bounds__(256, 2) precompute_kernel(
    const float* __restrict__ x, const float* __restrict__ eW1,
    const float* __restrict__ eb1)
{
    extern __shared__ float sm[];
    float* Xs = sm;               // [64][68]
    float* Ws = sm + 64 * 68;     // [64][256]

    const int n0 = blockIdx.x * 64;
    const int tid = threadIdx.x;

    for (int idx = tid; idx < 64 * 64; idx += 256) {
        int r = idx >> 6, c = idx & 63;
        int n = n0 + r;
        Xs[r * 68 + c] = (n < NN) ? x[n * 64 + c] : 0.f;
    }
    for (int idx = tid; idx < 64 * 256; idx += 256) {
        int k = idx >> 8, j = idx & 255;
        float v = (j < 128) ? eW1[(64 + k) * 128 + j]
                            : eW1[(128 + k) * 128 + (j - 128)];
        Ws[k * 256 + j] = v;
    }
    __syncthreads();

    const int tx = tid & 15;
    const int ty = tid >> 4;

    float acc[4][16];
    #pragma unroll
    for (int i = 0; i < 4; i++)
        #pragma unroll
        for (int j = 0; j < 16; j++) acc[i][j] = 0.f;

    #pragma unroll 4
    for (int k = 0; k < 64; k++) {
        float a[4];
        #pragma unroll
        for (int i = 0; i < 4; i++) a[i] = Xs[(ty * 4 + i) * 68 + k];
        const float4 b0 = *(const float4*)&Ws[k * 256 + tx * 16 + 0];
        const float4 b1 = *(const float4*)&Ws[k * 256 + tx * 16 + 4];
        const float4 b2 = *(const float4*)&Ws[k * 256 + tx * 16 + 8];
        const float4 b3 = *(const float4*)&Ws[k * 256 + tx * 16 + 12];
        float b[16] = {b0.x, b0.y, b0.z, b0.w, b1.x, b1.y, b1.z, b1.w,
                       b2.x, b2.y, b2.z, b2.w, b3.x, b3.y, b3.z, b3.w};
        #pragma unroll
        for (int i = 0; i < 4; i++)
            #pragma unroll
            for (int j = 0; j < 16; j++)
                acc[i][j] = fmaf(a[i], b[j], acc[i][j]);
    }

    const bool isPR = (tx < 8);
    float* dst = isPR ? g_PR : g_PC;
    int    cb  = isPR ? tx * 16 : (tx - 8) * 16;
    #pragma unroll
    for (int i = 0; i < 4; i++) {
        int n = n0 + ty * 4 + i;
        if (n >= NN) continue;
        #pragma unroll
        for (int jj = 0; jj < 16; jj++) {
            int m = cb + jj;
            float v = acc[i][jj] + (isPR ? eb1[m] : 0.f);
            dst[n * 128 + hperm(m)] = v;
        }
    }
}

// ---------------------------------------------------------------------------
// Precompute PX (fp32 exact, permuted cols, nb1 folded): PX = x @ nW1[0:64]
// ---------------------------------------------------------------------------
__global__ void __launch_bounds__(256, 2) precompute_px_kernel(
    const float* __restrict__ x, const float* __restrict__ nW1,
    const float* __restrict__ nb1)
{
    extern __shared__ float sm[];
    float* Xs = sm;               // [64][68]
    float* Ws = sm + 64 * 68;     // [64][128]

    const int n0 = blockIdx.x * 64;
    const int tid = threadIdx.x;

    for (int idx = tid; idx < 64 * 64; idx += 256) {
        int r = idx >> 6, c = idx & 63;
        int n = n0 + r;
        Xs[r * 68 + c] = (n < NN) ? x[n * 64 + c] : 0.f;
    }
    for (int idx = tid; idx < 64 * 128; idx += 256)
        Ws[idx] = nW1[idx];
    __syncthreads();

    const int tx = tid & 15;
    const int ty = tid >> 4;

    float acc[4][8];
    #pragma unroll
    for (int i = 0; i < 4; i++)
        #pragma unroll
        for (int j = 0; j < 8; j++) acc[i][j] = 0.f;

    #pragma unroll 4
    for (int k = 0; k < 64; k++) {
        float a[4];
        #pragma unroll
        for (int i = 0; i < 4; i++) a[i] = Xs[(ty * 4 + i) * 68 + k];
        const float4 b0 = *(const float4*)&Ws[k * 128 + tx * 8 + 0];
        const float4 b1 = *(const float4*)&Ws[k * 128 + tx * 8 + 4];
        float b[8] = {b0.x, b0.y, b0.z, b0.w, b1.x, b1.y, b1.z, b1.w};
        #pragma unroll
        for (int i = 0; i < 4; i++)
            #pragma unroll
            for (int j = 0; j < 8; j++)
                acc[i][j] = fmaf(a[i], b[j], acc[i][j]);
    }

    #pragma unroll
    for (int i = 0; i < 4; i++) {
        int n = n0 + ty * 4 + i;
        if (n >= NN) continue;
        #pragma unroll
        for (int jj = 0; jj < 8; jj++) {
            int m = tx * 8 + jj;
            g_PX[n * 128 + hperm(m)] = acc[i][jj] + nb1[m];
        }
    }
}

// ---------------------------------------------------------------------------
// Smem layout for persistent mma kernels (103168 B, 2 CTAs/SM)
// ---------------------------------------------------------------------------
constexpr int S_A   = 0;          // A [128][68] row-major (raw fp32)
constexpr int S_B1  = 8704;       // B1frag [pane=kk*16+nn][66]
constexpr int S_B2  = 17152;      // B2frag [pane=kk*8+nn][66]
constexpr int S_EB2 = 25728;      // bias2 [64]
constexpr int MMA_SMEM_BYTES = 25792 * 4;   // 103168

// ---------------------------------------------------------------------------
// Edge kernel — persistent, barrier-free main loop, per-warp A slabs,
// shuffle-free float4 gathers via hidden-dim permutation.
// ---------------------------------------------------------------------------
__global__ void __launch_bounds__(256, 2) edge_kernel(
    const float* __restrict__ edge_attr,
    const int*   __restrict__ edge_index,   // [2][NE]
    const float* __restrict__ eW1,
    const float* __restrict__ eW2,
    const float* __restrict__ eb2,
    float* __restrict__ out_edge)
{
    extern __shared__ float sm[];
    uint32_t* smu = reinterpret_cast<uint32_t*>(sm);
    const uint32_t sbase = smem_u32(sm);

    const int tid  = threadIdx.x;
    const int lane = tid & 31;
    const int w    = tid >> 5;
    const int gr   = lane >> 2;
    const int ct   = lane & 3;
    const int s0   = ct >> 1;
    const int s1   = 2 + (ct >> 1);
    const int sel  = ct & 1;
    const int even = (ct & 1) == 0;
    const int qb   = 4 * (ct >> 1);
    const int r1   = 16 * w + gr;
    const int r2   = r1 + 8;

    const uint32_t slabBase = sbase + (S_A + 16 * w * 68) * 4;

    // ---- prologue: B fragments + eb2 (block-cooperative, once) ----
    for (int t = tid; t < 2048; t += 256) {
        int k = t >> 5, n4 = (t & 31) << 2;
        float4 v = *(const float4*)&eW1[k * 128 + n4];
        int pane = (k >> 3) * 16 + (n4 >> 3);
        int j    = (k >> 2) & 1;
        int ln0  = ((n4 & 7) << 2) | (k & 3);
        uint32_t* p = &smu[S_B1 + pane * 66 + j];
        p[(ln0 + 0)  * 2] = f32_to_tf32(v.x);
        p[(ln0 + 4)  * 2] = f32_to_tf32(v.y);
        p[(ln0 + 8)  * 2] = f32_to_tf32(v.z);
        p[(ln0 + 12) * 2] = f32_to_tf32(v.w);
    }
    for (int t = tid; t < 2048; t += 256) {
        int k = t >> 4, n4 = (t & 15) << 2;
        float4 v = *(const float4*)&eW2[k * 64 + n4];
        int pane = (k >> 3) * 8 + (n4 >> 3);
        int j    = (k >> 2) & 1;
        int ln0  = ((n4 & 7) << 2) | (k & 3);
        uint32_t* p = &smu[S_B2 + pane * 66 + j];
        p[(ln0 + 0)  * 2] = f32_to_tf32(v.x);
        p[(ln0 + 4)  * 2] = f32_to_tf32(v.y);
        p[(ln0 + 8)  * 2] = f32_to_tf32(v.z);
        p[(ln0 + 12) * 2] = f32_to_tf32(v.w);
    }
    if (tid < 64) sm[S_EB2 + tid] = eb2[tid];

    // ---- per-warp A slab for first tile ----
    {
        int e0 = blockIdx.x * 128;
        #pragma unroll
        for (int i = 0; i < 8; i++) {
            int idx = lane + 32 * i;
            int rl = idx >> 4, c4 = (idx & 15) << 2;
            CP_ASYNC16(slabBase + (rl * 68 + c4) * 4,
                       edge_attr + (size_t)(e0 + 16 * w + rl) * 64 + c4);
        }
        CP_COMMIT();
    }
    __syncthreads();   // B fragments visible; the ONLY block barrier
    CP_WAIT0();
    __syncwarp();

    // ---- persistent tile loop (no block barriers) ----
    for (int tile = blockIdx.x; tile < NTILES; tile += PGRID) {
        const int e0 = tile * 128;

        const int re1 = __ldg(&edge_index[e0 + r1]);
        const int re2 = __ldg(&edge_index[e0 + r2]);
        const int ce1 = __ldg(&edge_index[NE + e0 + r1]);
        const int ce2 = __ldg(&edge_index[NE + e0 + r2]);

        // layer-1 mma (A from own slab, conflict-free scalar LDS)
        float acc[16][4];
        #pragma unroll
        for (int nn = 0; nn < 16; nn++) {
            acc[nn][0] = acc[nn][1] = acc[nn][2] = acc[nn][3] = 0.f;
        }
        #pragma unroll
        for (int kk = 0; kk < 8; kk++) {
            const int col = kk * 8 + ct;
            uint32_t a[4];
            a[0] = smu[S_A + r1 * 68 + col];
            a[1] = smu[S_A + r2 * 68 + col];
            a[2] = smu[S_A + r1 * 68 + col + 4];
            a[3] = smu[S_A + r2 * 68 + col + 4];
            #pragma unroll
            for (int nn = 0; nn < 16; nn++) {
                uint32_t b[2];
                const uint2 bv = *(const uint2*)&smu[S_B1 + (kk * 16 + nn) * 66 + lane * 2];
                b[0] = bv.x; b[1] = bv.y;
                mma_tf32(acc[nn], a, b);
            }
        }
        __syncwarp();   // all lanes done reading this warp's slab

        // per-warp prefetch of next tile's slab
        {
            int ntile = tile + PGRID;
            if (ntile < NTILES) {
                int ne0 = ntile * 128;
                #pragma unroll
                for (int i = 0; i < 8; i++) {
                    int idx = lane + 32 * i;
                    int rl = idx >> 4, c4 = (idx & 15) << 2;
                    CP_ASYNC16(slabBase + (rl * 68 + c4) * 4,
                               edge_attr + (size_t)(ne0 + 16 * w + rl) * 64 + c4);
                }
            }
            CP_COMMIT();
        }

        // ---- epilogue: shuffle-free float4 gathers (permuted tables) ----
        // H = rna(relu(C1 + PR'(incl. eb1) + PC'))
        {
            const float* PR1 = g_PR + (size_t)re1 * 128;
            const float* PR2 = g_PR + (size_t)re2 * 128;
            const float* PC1 = g_PC + (size_t)ce1 * 128;
            const float* PC2 = g_PC + (size_t)ce2 * 128;
            #pragma unroll
            for (int j = 0; j < 8; j++) {
                const int off = 16 * j + 4 * ct;
                float4 a1 = *(const float4*)&PR1[off];
                float4 c1 = *(const float4*)&PC1[off];
                float4 a2 = *(const float4*)&PR2[off];
                float4 c2 = *(const float4*)&PC2[off];
                const int n0i = 2 * j, n1i = 2 * j + 1;
                acc[n0i][0] = RELU_RNA(acc[n0i][0] + a1.x + c1.x);
                acc[n0i][1] = RELU_RNA(acc[n0i][1] + a1.y + c1.y);
                acc[n0i][2] = RELU_RNA(acc[n0i][2] + a2.x + c2.x);
                acc[n0i][3] = RELU_RNA(acc[n0i][3] + a2.y + c2.y);
                acc[n1i][0] = RELU_RNA(acc[n1i][0] + a1.z + c1.z);
                acc[n1i][1] = RELU_RNA(acc[n1i][1] + a1.w + c1.w);
                acc[n1i][2] = RELU_RNA(acc[n1i][2] + a2.z + c2.z);
                acc[n1i][3] = RELU_RNA(acc[n1i][3] + a2.w + c2.w);
            }
        }

        // quad-shuffle transpose -> layer-2 A fragments
        #pragma unroll
        for (int kk = 0; kk < 16; kk++) {
            float t0 = __shfl_sync(0xffffffffu, acc[kk][0], s0, 4);
            float t1 = __shfl_sync(0xffffffffu, acc[kk][1], s0, 4);
            float t2 = __shfl_sync(0xffffffffu, acc[kk][2], s0, 4);
            float t3 = __shfl_sync(0xffffffffu, acc[kk][3], s0, 4);
            float u0 = __shfl_sync(0xffffffffu, acc[kk][0], s1, 4);
            float u1 = __shfl_sync(0xffffffffu, acc[kk][1], s1, 4);
            float u2 = __shfl_sync(0xffffffffu, acc[kk][2], s1, 4);
            float u3 = __shfl_sync(0xffffffffu, acc[kk][3], s1, 4);
            acc[kk][0] = sel ? t1 : t0;
            acc[kk][1] = sel ? t3 : t2;
            acc[kk][2] = sel ? u1 : u0;
            acc[kk][3] = sel ? u3 : u2;
        }

        // layer-2 mma
        float acc2[8][4];
        #pragma unroll
        for (int nn = 0; nn < 8; nn++) {
            acc2[nn][0] = acc2[nn][1] = acc2[nn][2] = acc2[nn][3] = 0.f;
        }
        #pragma unroll
        for (int kk = 0; kk < 16; kk++) {
            uint32_t a[4];
            a[0] = __float_as_uint(acc[kk][0]);
            a[1] = __float_as_uint(acc[kk][1]);
            a[2] = __float_as_uint(acc[kk][2]);
            a[3] = __float_as_uint(acc[kk][3]);
            #pragma unroll
            for (int nn = 0; nn < 8; nn++) {
                uint32_t b[2];
                const uint2 bv = *(const uint2*)&smu[S_B2 + (kk * 8 + nn) * 66 + lane * 2];
                b[0] = bv.x; b[1] = bv.y;
                mma_tf32(acc2[nn], a, b);
            }
        }

        // output: lane-pair exchange -> float4 stores + red.v4
        {
            const int row  = even ? r1 : r2;
            const int ced  = even ? ce1 : ce2;
            float* op = out_edge + (size_t)(e0 + row) * 64;
            float* mp = g_msg + (size_t)ced * 64;
            #pragma unroll
            for (int nn = 0; nn < 8; nn++) {
                float sa = __shfl_xor_sync(0xffffffffu, acc2[nn][0], 1);
                float sb = __shfl_xor_sync(0xffffffffu, acc2[nn][1], 1);
                float sc = __shfl_xor_sync(0xffffffffu, acc2[nn][2], 1);
                float sd = __shfl_xor_sync(0xffffffffu, acc2[nn][3], 1);
                int base = nn * 8 + qb;
                float4 bb = *(const float4*)&sm[S_EB2 + base];
                float4 o;
                if (even) {
                    o = make_float4(acc2[nn][0] + bb.x, acc2[nn][1] + bb.y,
                                    sa + bb.z, sb + bb.w);
                } else {
                    o = make_float4(sc + bb.x, sd + bb.y,
                                    acc2[nn][2] + bb.z, acc2[nn][3] + bb.w);
                }
                *(float4*)(op + base) = o;
                asm volatile("red.global.add.v4.f32 [%0], {%1,%2,%3,%4};"
                             :: "l"(mp + base), "f"(o.x), "f"(o.y), "f"(o.z), "f"(o.w)
                             : "memory");
            }
        }

        CP_WAIT0();
        __syncwarp();
    }
}

// ---------------------------------------------------------------------------
// Node kernel — same skeleton; shuffle-free permuted PX gathers; no atomics.
// ---------------------------------------------------------------------------
__global__ void __launch_bounds__(256, 2) node_kernel(
    const float* __restrict__ nW1,
    const float* __restrict__ nW2, const float* __restrict__ nb2,
    float* __restrict__ out_node)
{
    extern __shared__ float sm[];
    uint32_t* smu = reinterpret_cast<uint32_t*>(sm);
    const uint32_t sbase = smem_u32(sm);

    const int tid  = threadIdx.x;
    const int lane = tid & 31;
    const int w    = tid >> 5;
    const int gr   = lane >> 2;
    const int ct   = lane & 3;
    const int s0   = ct >> 1;
    const int s1   = 2 + (ct >> 1);
    const int sel  = ct & 1;
    const int even = (ct & 1) == 0;
    const int qb   = 4 * (ct >> 1);
    const int r1   = 16 * w + gr;
    const int r2   = r1 + 8;

    const uint32_t slabBase = sbase + (S_A + 16 * w * 68) * 4;

    // ---- prologue ----
    for (int t = tid; t < 2048; t += 256) {
        int k = t >> 5, n4 = (t & 31) << 2;
        float4 v = *(const float4*)&nW1[(64 + k) * 128 + n4];
        int pane = (k >> 3) * 16 + (n4 >> 3);
        int j    = (k >> 2) & 1;
        int ln0  = ((n4 & 7) << 2) | (k & 3);
        uint32_t* p = &smu[S_B1 + pane * 66 + j];
        p[(ln0 + 0)  * 2] = f32_to_tf32(v.x);
        p[(ln0 + 4)  * 2] = f32_to_tf32(v.y);
        p[(ln0 + 8)  * 2] = f32_to_tf32(v.z);
        p[(ln0 + 12) * 2] = f32_to_tf32(v.w);
    }
    for (int t = tid; t < 2048; t += 256) {
        int k = t >> 4, n4 = (t & 15) << 2;
        float4 v = *(const float4*)&nW2[k * 64 + n4];
        int pane = (k >> 3) * 8 + (n4 >> 3);
        int j    = (k >> 2) & 1;
        int ln0  = ((n4 & 7) << 2) | (k & 3);
        uint32_t* p = &smu[S_B2 + pane * 66 + j];
        p[(ln0 + 0)  * 2] = f32_to_tf32(v.x);
        p[(ln0 + 4)  * 2] = f32_to_tf32(v.y);
        p[(ln0 + 8)  * 2] = f32_to_tf32(v.z);
        p[(ln0 + 12) * 2] = f32_to_tf32(v.w);
    }
    if (tid < 64) sm[S_EB2 + tid] = nb2[tid];

    {
        int n0 = blockIdx.x * 128;
        #pragma unroll
        for (int i = 0; i < 8; i++) {
            int idx = lane + 32 * i;
            int rl = idx >> 4, c4 = (idx & 15) << 2;
            int row = n0 + 16 * w + rl;
            uint32_t nbytes = (row < NN) ? 16u : 0u;
            const float* src = g_msg + (size_t)min(row, NN - 1) * 64 + c4;
            CP_ASYNC16_Z(slabBase + (rl * 68 + c4) * 4, src, nbytes);
        }
        CP_COMMIT();
    }
    __syncthreads();
    CP_WAIT0();
    __syncwarp();

    for (int tile = blockIdx.x; tile < NTILN; tile += PGRID) {
        const int n0 = tile * 128;

        float acc[16][4];
        #pragma unroll
        for (int nn = 0; nn < 16; nn++) {
            acc[nn][0] = acc[nn][1] = acc[nn][2] = acc[nn][3] = 0.f;
        }
        #pragma unroll
        for (int kk = 0; kk < 8; kk++) {
            const int col = kk * 8 + ct;
            uint32_t a[4];
            a[0] = smu[S_A + r1 * 68 + col];
            a[1] = smu[S_A + r2 * 68 + col];
            a[2] = smu[S_A + r1 * 68 + col + 4];
            a[3] = smu[S_A + r2 * 68 + col + 4];
            #pragma unroll
            for (int nn = 0; nn < 16; nn++) {
                uint32_t b[2];
                const uint2 bv = *(const uint2*)&smu[S_B1 + (kk * 16 + nn) * 66 + lane * 2];
                b[0] = bv.x; b[1] = bv.y;
                mma_tf32(acc[nn], a, b);
            }
        }
        __syncwarp();

        {
            int ntile = tile + PGRID;
            if (ntile < NTILN) {
                int nn0 = ntile * 128;
                #pragma unroll
                for (int i = 0; i < 8; i++) {
                    int idx = lane + 32 * i;
                    int rl = idx >> 4, c4 = (idx & 15) << 2;
                    int row = nn0 + 16 * w + rl;
                    uint32_t nbytes = (row < NN) ? 16u : 0u;
                    const float* src = g_msg + (size_t)min(row, NN - 1) * 64 + c4;
                    CP_ASYNC16_Z(slabBase + (rl * 68 + c4) * 4, src, nbytes);
                }
            }
            CP_COMMIT();
        }

        // epilogue: shuffle-free float4 PX gathers (nb1 already folded)
        {
            const float* PX1 = g_PX + (size_t)min(n0 + r1, NN - 1) * 128;
            const float* PX2 = g_PX + (size_t)min(n0 + r2, NN - 1) * 128;
            #pragma unroll
            for (int j = 0; j < 8; j++) {
                const int off = 16 * j + 4 * ct;
                float4 a1 = *(const float4*)&PX1[off];
                float4 a2 = *(const float4*)&PX2[off];
                const int n0i = 2 * j, n1i = 2 * j + 1;
                acc[n0i][0] = RELU_RNA(acc[n0i][0] + a1.x);
                acc[n0i][1] = RELU_RNA(acc[n0i][1] + a1.y);
                acc[n0i][2] = RELU_RNA(acc[n0i][2] + a2.x);
                acc[n0i][3] = RELU_RNA(acc[n0i][3] + a2.y);
                acc[n1i][0] = RELU_RNA(acc[n1i][0] + a1.z);
                acc[n1i][1] = RELU_RNA(acc[n1i][1] + a1.w);
                acc[n1i][2] = RELU_RNA(acc[n1i][2] + a2.z);
                acc[n1i][3] = RELU_RNA(acc[n1i][3] + a2.w);
            }
        }

        #pragma unroll
        for (int kk = 0; kk < 16; kk++) {
            float t0 = __shfl_sync(0xffffffffu, acc[kk][0], s0, 4);
            float t1 = __shfl_sync(0xffffffffu, acc[kk][1], s0, 4);
            float t2 = __shfl_sync(0xffffffffu, acc[kk][2], s0, 4);
            float t3 = __shfl_sync(0xffffffffu, acc[kk][3], s0, 4);
            float u0 = __shfl_sync(0xffffffffu, acc[kk][0], s1, 4);
            float u1 = __shfl_sync(0xffffffffu, acc[kk][1], s1, 4);
            float u2 = __shfl_sync(0xffffffffu, acc[kk][2], s1, 4);
            float u3 = __shfl_sync(0xffffffffu, acc[kk][3], s1, 4);
            acc[kk][0] = sel ? t1 : t0;
            acc[kk][1] = sel ? t3 : t2;
            acc[kk][2] = sel ? u1 : u0;
            acc[kk][3] = sel ? u3 : u2;
        }

        float acc2[8][4];
        #pragma unroll
        for (int nn = 0; nn < 8; nn++) {
            acc2[nn][0] = acc2[nn][1] = acc2[nn][2] = acc2[nn][3] = 0.f;
        }
        #pragma unroll
        for (int kk = 0; kk < 16; kk++) {
            uint32_t a[4];
            a[0] = __float_as_uint(acc[kk][0]);
            a[1] = __float_as_uint(acc[kk][1]);
            a[2] = __float_as_uint(acc[kk][2]);
            a[3] = __float_as_uint(acc[kk][3]);
            #pragma unroll
            for (int nn = 0; nn < 8; nn++) {
                uint32_t b[2];
                const uint2 bv = *(const uint2*)&smu[S_B2 + (kk * 8 + nn) * 66 + lane * 2];
                b[0] = bv.x; b[1] = bv.y;
                mma_tf32(acc2[nn], a, b);
            }
        }

        {
            const int row = even ? r1 : r2;
            const int n   = n0 + row;
            float* op = out_node + (size_t)n * 64;
            #pragma unroll
            for (int nn = 0; nn < 8; nn++) {
                float sa = __shfl_xor_sync(0xffffffffu, acc2[nn][0], 1);
                float sb = __shfl_xor_sync(0xffffffffu, acc2[nn][1], 1);
                float sc = __shfl_xor_sync(0xffffffffu, acc2[nn][2], 1);
                float sd = __shfl_xor_sync(0xffffffffu, acc2[nn][3], 1);
                int base = nn * 8 + qb;
                float4 bb = *(const float4*)&sm[S_EB2 + base];
                float4 o;
                if (even) {
                    o = make_float4(acc2[nn][0] + bb.x, acc2[nn][1] + bb.y,
                                    sa + bb.z, sb + bb.w);
                } else {
                    o = make_float4(sc + bb.x, sd + bb.y,
                                    acc2[nn][2] + bb.z, acc2[nn][3] + bb.w);
                }
                if (n < NN) *(float4*)(op + base) = o;
            }
        }

        CP_WAIT0();
        __syncwarp();
    }
}

// ---------------------------------------------------------------------------
extern "C" void kernel_launch(void* const* d_in, const int* in_sizes, int n_in,
                              void* d_out, int out_size)
{
    const float* x    = (const float*)d_in[0];
    const int*   ei   = (const int*)  d_in[1];
    const float* ea   = (const float*)d_in[2];
    const float* eW1  = (const float*)d_in[3];
    const float* eb1  = (const float*)d_in[4];
    const float* eW2  = (const float*)d_in[5];
    const float* eb2  = (const float*)d_in[6];
    const float* nW1  = (const float*)d_in[7];
    const float* nb1  = (const float*)d_in[8];
    const float* nW2  = (const float*)d_in[9];
    const float* nb2  = (const float*)d_in[10];

    float* out_node = (float*)d_out;             // [NN, 64]
    float* out_edge = (float*)d_out + NN * ND;   // [NE, 64]

    const int smem_pre = (64 * 68 + 64 * 256) * 4;   // 82944
    const int smem_px  = (64 * 68 + 64 * 128) * 4;   // 50176

    cudaFuncSetAttribute(precompute_kernel,
        cudaFuncAttributeMaxDynamicSharedMemorySize, smem_pre);
    cudaFuncSetAttribute(precompute_px_kernel,
        cudaFuncAttributeMaxDynamicSharedMemorySize, smem_px);
    cudaFuncSetAttribute(edge_kernel,
        cudaFuncAttributeMaxDynamicSharedMemorySize, MMA_SMEM_BYTES);
    cudaFuncSetAttribute(node_kernel,
        cudaFuncAttributeMaxDynamicSharedMemorySize, MMA_SMEM_BYTES);

    zero_msg_kernel<<<(NN * ED / 4) / 256, 256>>>();
    precompute_kernel<<<(NN + 63) / 64, 256, smem_pre>>>(x, eW1, eb1);
    precompute_px_kernel<<<(NN + 63) / 64, 256, smem_px>>>(x, nW1, nb1);
    edge_kernel<<<PGRID, 256, MMA_SMEM_BYTES>>>(ea, ei, eW1, eW2, eb2, out_edge);
    node_kernel<<<PGRID, 256, MMA_SMEM_BYTES>>>(nW1, nW2, nb2, out_node);
}

// round 16
// speedup vs baseline: 1.2029x; 1.1703x over previous
#include <cuda_runtime.h>
#include <cuda_fp16.h>
#include <cstdint>

// Problem constants
constexpr int NN  = 50000;   // nodes
constexpr int NE  = 800000;  // edges
constexpr int ND  = 64;      // node dim
constexpr int ED  = 64;      // edge dim
constexpr int HID = 128;     // hidden

constexpr int NTILES = NE / 128;            // 6250 edge tiles
constexpr int NTILN  = (NN + 127) / 128;    // 391 node tiles
constexpr int PGRID  = 296;                 // 2 CTAs x 148 SMs, persistent

// Scratch (device globals: allocation-free)
// Tables are fp16, hidden dim permuted by hperm16 (pair-packed for uint4
// gathers), with eb1 folded into PR and nb1 folded into PX.
__device__ __half g_PR[NN * HID];   // perm16(x @ eW1[64:128] + eb1)
__device__ __half g_PC[NN * HID];   // perm16(x @ eW1[128:192])
__device__ __half g_PX[NN * HID];   // perm16(x @ nW1[0:64] + nb1)
__device__ float  g_msg[NN * ED];   // scatter-add accumulator (fp32)

// fp16 table permutation: mma hidden position m -> physical half offset.
// Packs (nn=4P..4P+3, s=0..1) for lane ct into one 16-byte span.
__host__ __device__ __forceinline__ int hperm16(int m) {
    return 32 * (m >> 5) + 8 * ((m & 7) >> 1) + 2 * ((m >> 3) & 3) + (m & 1);
}

// ---------------------------------------------------------------------------
// helpers
// ---------------------------------------------------------------------------
__device__ __forceinline__ uint32_t f32_to_tf32(float f) {
    uint32_t u;
    asm("cvt.rna.tf32.f32 %0, %1;" : "=r"(u) : "f"(f));
    return u;
}

__device__ __forceinline__ void mma_tf32(float d[4], const uint32_t a[4],
                                         const uint32_t b[2]) {
    asm volatile(
        "mma.sync.aligned.m16n8k8.row.col.f32.tf32.tf32.f32 "
        "{%0,%1,%2,%3}, {%4,%5,%6,%7}, {%8,%9}, {%0,%1,%2,%3};"
        : "+f"(d[0]), "+f"(d[1]), "+f"(d[2]), "+f"(d[3])
        : "r"(a[0]), "r"(a[1]), "r"(a[2]), "r"(a[3]), "r"(b[0]), "r"(b[1]));
}

__device__ __forceinline__ uint32_t smem_u32(const void* p) {
    uint32_t a;
    asm("{ .reg .u64 t; cvta.to.shared.u64 t, %1; cvt.u32.u64 %0, t; }"
        : "=r"(a) : "l"(p));
    return a;
}

__device__ __forceinline__ float2 h2f(uint32_t u) {
    __half2 h = *reinterpret_cast<__half2*>(&u);
    return __half22float2(h);
}

#define CP_ASYNC16(dst_u32, src_ptr) \
    asm volatile("cp.async.cg.shared.global [%0], [%1], 16;" \
                 :: "r"(dst_u32), "l"(src_ptr))
#define CP_ASYNC16_Z(dst_u32, src_ptr, src_bytes) \
    asm volatile("cp.async.cg.shared.global [%0], [%1], 16, %2;" \
                 :: "r"(dst_u32), "l"(src_ptr), "r"(src_bytes))
#define CP_COMMIT()  asm volatile("cp.async.commit_group;")
#define CP_WAIT0()   asm volatile("cp.async.wait_group 0;" ::: "memory")

#define RELU_RNA(x) __uint_as_float(f32_to_tf32(fmaxf((x), 0.f)))

// ---------------------------------------------------------------------------
__global__ void zero_msg_kernel() {
    int i = blockIdx.x * blockDim.x + threadIdx.x;
    reinterpret_cast<float4*>(g_msg)[i] = make_float4(0.f, 0.f, 0.f, 0.f);
}

// ---------------------------------------------------------------------------
// Precompute PR/PC (fp16 tables, permuted, eb1 folded into PR):
// GEMM [NN,64] @ [64,256]
// ---------------------------------------------------------------------------
__global__ void __launch_bounds__(256, 2) precompute_kernel(
    const float* __restrict__ x, const float* __restrict__ eW1,
    const float* __restrict__ eb1)
{
    extern __shared__ float sm[];
    float* Xs = sm;               // [64][68]
    float* Ws = sm + 64 * 68;     // [64][256]

    const int n0 = blockIdx.x * 64;
    const int tid = threadIdx.x;

    for (int idx = tid; idx < 64 * 64; idx += 256) {
        int r = idx >> 6, c = idx & 63;
        int n = n0 + r;
        Xs[r * 68 + c] = (n < NN) ? x[n * 64 + c] : 0.f;
    }
    for (int idx = tid; idx < 64 * 256; idx += 256) {
        int k = idx >> 8, j = idx & 255;
        float v = (j < 128) ? eW1[(64 + k) * 128 + j]
                            : eW1[(128 + k) * 128 + (j - 128)];
        Ws[k * 256 + j] = v;
    }
    __syncthreads();

    const int tx = tid & 15;
    const int ty = tid >> 4;

    float acc[4][16];
    #pragma unroll
    for (int i = 0; i < 4; i++)
        #pragma unroll
        for (int j = 0; j < 16; j++) acc[i][j] = 0.f;

    #pragma unroll 4
    for (int k = 0; k < 64; k++) {
        float a[4];
        #pragma unroll
        for (int i = 0; i < 4; i++) a[i] = Xs[(ty * 4 + i) * 68 + k];
        const float4 b0 = *(const float4*)&Ws[k * 256 + tx * 16 + 0];
        const float4 b1 = *(const float4*)&Ws[k * 256 + tx * 16 + 4];
        const float4 b2 = *(const float4*)&Ws[k * 256 + tx * 16 + 8];
        const float4 b3 = *(const float4*)&Ws[k * 256 + tx * 16 + 12];
        float b[16] = {b0.x, b0.y, b0.z, b0.w, b1.x, b1.y, b1.z, b1.w,
                       b2.x, b2.y, b2.z, b2.w, b3.x, b3.y, b3.z, b3.w};
        #pragma unroll
        for (int i = 0; i < 4; i++)
            #pragma unroll
            for (int j = 0; j < 16; j++)
                acc[i][j] = fmaf(a[i], b[j], acc[i][j]);
    }

    const bool isPR = (tx < 8);
    __half* dst = isPR ? g_PR : g_PC;
    int     cb  = isPR ? tx * 16 : (tx - 8) * 16;
    #pragma unroll
    for (int i = 0; i < 4; i++) {
        int n = n0 + ty * 4 + i;
        if (n >= NN) continue;
        #pragma unroll
        for (int jj = 0; jj < 16; jj++) {
            int m = cb + jj;
            float v = acc[i][jj] + (isPR ? eb1[m] : 0.f);
            dst[(size_t)n * 128 + hperm16(m)] = __float2half_rn(v);
        }
    }
}

// ---------------------------------------------------------------------------
// Precompute PX (fp16, permuted, nb1 folded): PX = x @ nW1[0:64]
// ---------------------------------------------------------------------------
__global__ void __launch_bounds__(256, 2) precompute_px_kernel(
    const float* __restrict__ x, const float* __restrict__ nW1,
    const float* __restrict__ nb1)
{
    extern __shared__ float sm[];
    float* Xs = sm;               // [64][68]
    float* Ws = sm + 64 * 68;     // [64][128]

    const int n0 = blockIdx.x * 64;
    const int tid = threadIdx.x;

    for (int idx = tid; idx < 64 * 64; idx += 256) {
        int r = idx >> 6, c = idx & 63;
        int n = n0 + r;
        Xs[r * 68 + c] = (n < NN) ? x[n * 64 + c] : 0.f;
    }
    for (int idx = tid; idx < 64 * 128; idx += 256)
        Ws[idx] = nW1[idx];
    __syncthreads();

    const int tx = tid & 15;
    const int ty = tid >> 4;

    float acc[4][8];
    #pragma unroll
    for (int i = 0; i < 4; i++)
        #pragma unroll
        for (int j = 0; j < 8; j++) acc[i][j] = 0.f;

    #pragma unroll 4
    for (int k = 0; k < 64; k++) {
        float a[4];
        #pragma unroll
        for (int i = 0; i < 4; i++) a[i] = Xs[(ty * 4 + i) * 68 + k];
        const float4 b0 = *(const float4*)&Ws[k * 128 + tx * 8 + 0];
        const float4 b1 = *(const float4*)&Ws[k * 128 + tx * 8 + 4];
        float b[8] = {b0.x, b0.y, b0.z, b0.w, b1.x, b1.y, b1.z, b1.w};
        #pragma unroll
        for (int i = 0; i < 4; i++)
            #pragma unroll
            for (int j = 0; j < 8; j++)
                acc[i][j] = fmaf(a[i], b[j], acc[i][j]);
    }

    #pragma unroll
    for (int i = 0; i < 4; i++) {
        int n = n0 + ty * 4 + i;
        if (n >= NN) continue;
        #pragma unroll
        for (int jj = 0; jj < 8; jj++) {
            int m = tx * 8 + jj;
            g_PX[(size_t)n * 128 + hperm16(m)] =
                __float2half_rn(acc[i][jj] + nb1[m]);
        }
    }
}

// ---------------------------------------------------------------------------
// Smem layout for persistent mma kernels (103168 B, 2 CTAs/SM)
// ---------------------------------------------------------------------------
constexpr int S_A   = 0;          // A [128][68] row-major (raw fp32)
constexpr int S_B1  = 8704;       // B1frag [pane=kk*16+nn][66]
constexpr int S_B2  = 17152;      // B2frag [pane=kk*8+nn][66]
constexpr int S_EB2 = 25728;      // bias2 [64]
constexpr int MMA_SMEM_BYTES = 25792 * 4;   // 103168

// ---------------------------------------------------------------------------
// Edge kernel — persistent, barrier-free main loop, per-warp A slabs,
// fp16 uint4 gathers (one 16-B load per table per 4-octet group).
// ---------------------------------------------------------------------------
__global__ void __launch_bounds__(256, 2) edge_kernel(
    const float* __restrict__ edge_attr,
    const int*   __restrict__ edge_index,   // [2][NE]
    const float* __restrict__ eW1,
    const float* __restrict__ eW2,
    const float* __restrict__ eb2,
    float* __restrict__ out_edge)
{
    extern __shared__ float sm[];
    uint32_t* smu = reinterpret_cast<uint32_t*>(sm);
    const uint32_t sbase = smem_u32(sm);

    const int tid  = threadIdx.x;
    const int lane = tid & 31;
    const int w    = tid >> 5;
    const int gr   = lane >> 2;
    const int ct   = lane & 3;
    const int s0   = ct >> 1;
    const int s1   = 2 + (ct >> 1);
    const int sel  = ct & 1;
    const int even = (ct & 1) == 0;
    const int qb   = 4 * (ct >> 1);
    const int r1   = 16 * w + gr;
    const int r2   = r1 + 8;

    const uint32_t slabBase = sbase + (S_A + 16 * w * 68) * 4;

    // ---- prologue: B fragments + eb2 (block-cooperative, once) ----
    for (int t = tid; t < 2048; t += 256) {
        int k = t >> 5, n4 = (t & 31) << 2;
        float4 v = *(const float4*)&eW1[k * 128 + n4];
        int pane = (k >> 3) * 16 + (n4 >> 3);
        int j    = (k >> 2) & 1;
        int ln0  = ((n4 & 7) << 2) | (k & 3);
        uint32_t* p = &smu[S_B1 + pane * 66 + j];
        p[(ln0 + 0)  * 2] = f32_to_tf32(v.x);
        p[(ln0 + 4)  * 2] = f32_to_tf32(v.y);
        p[(ln0 + 8)  * 2] = f32_to_tf32(v.z);
        p[(ln0 + 12) * 2] = f32_to_tf32(v.w);
    }
    for (int t = tid; t < 2048; t += 256) {
        int k = t >> 4, n4 = (t & 15) << 2;
        float4 v = *(const float4*)&eW2[k * 64 + n4];
        int pane = (k >> 3) * 8 + (n4 >> 3);
        int j    = (k >> 2) & 1;
        int ln0  = ((n4 & 7) << 2) | (k & 3);
        uint32_t* p = &smu[S_B2 + pane * 66 + j];
        p[(ln0 + 0)  * 2] = f32_to_tf32(v.x);
        p[(ln0 + 4)  * 2] = f32_to_tf32(v.y);
        p[(ln0 + 8)  * 2] = f32_to_tf32(v.z);
        p[(ln0 + 12) * 2] = f32_to_tf32(v.w);
    }
    if (tid < 64) sm[S_EB2 + tid] = eb2[tid];

    // ---- per-warp A slab for first tile ----
    {
        int e0 = blockIdx.x * 128;
        #pragma unroll
        for (int i = 0; i < 8; i++) {
            int idx = lane + 32 * i;
            int rl = idx >> 4, c4 = (idx & 15) << 2;
            CP_ASYNC16(slabBase + (rl * 68 + c4) * 4,
                       edge_attr + (size_t)(e0 + 16 * w + rl) * 64 + c4);
        }
        CP_COMMIT();
    }
    __syncthreads();   // B fragments visible; the ONLY block barrier
    CP_WAIT0();
    __syncwarp();

    // ---- persistent tile loop (no block barriers) ----
    for (int tile = blockIdx.x; tile < NTILES; tile += PGRID) {
        const int e0 = tile * 128;

        const int re1 = __ldg(&edge_index[e0 + r1]);
        const int re2 = __ldg(&edge_index[e0 + r2]);
        const int ce1 = __ldg(&edge_index[NE + e0 + r1]);
        const int ce2 = __ldg(&edge_index[NE + e0 + r2]);

        // layer-1 mma (A from own slab, conflict-free scalar LDS)
        float acc[16][4];
        #pragma unroll
        for (int nn = 0; nn < 16; nn++) {
            acc[nn][0] = acc[nn][1] = acc[nn][2] = acc[nn][3] = 0.f;
        }
        #pragma unroll
        for (int kk = 0; kk < 8; kk++) {
            const int col = kk * 8 + ct;
            uint32_t a[4];
            a[0] = smu[S_A + r1 * 68 + col];
            a[1] = smu[S_A + r2 * 68 + col];
            a[2] = smu[S_A + r1 * 68 + col + 4];
            a[3] = smu[S_A + r2 * 68 + col + 4];
            #pragma unroll
            for (int nn = 0; nn < 16; nn++) {
                uint32_t b[2];
                const uint2 bv = *(const uint2*)&smu[S_B1 + (kk * 16 + nn) * 66 + lane * 2];
                b[0] = bv.x; b[1] = bv.y;
                mma_tf32(acc[nn], a, b);
            }
        }
        __syncwarp();   // all lanes done reading this warp's slab

        // per-warp prefetch of next tile's slab
        {
            int ntile = tile + PGRID;
            if (ntile < NTILES) {
                int ne0 = ntile * 128;
                #pragma unroll
                for (int i = 0; i < 8; i++) {
                    int idx = lane + 32 * i;
                    int rl = idx >> 4, c4 = (idx & 15) << 2;
                    CP_ASYNC16(slabBase + (rl * 68 + c4) * 4,
                               edge_attr + (size_t)(ne0 + 16 * w + rl) * 64 + c4);
                }
            }
            CP_COMMIT();
        }

        // ---- epilogue: fp16 uint4 gathers, 4 P-groups of 4 octets ----
        // H = rna(relu(C1 + PR'(incl. eb1) + PC'))
        {
            const __half* PR1 = g_PR + (size_t)re1 * 128;
            const __half* PR2 = g_PR + (size_t)re2 * 128;
            const __half* PC1 = g_PC + (size_t)ce1 * 128;
            const __half* PC2 = g_PC + (size_t)ce2 * 128;
            #pragma unroll
            for (int P = 0; P < 4; P++) {
                const int off = 32 * P + 8 * ct;   // halfs
                uint4 A1 = *(const uint4*)(PR1 + off);
                uint4 C1 = *(const uint4*)(PC1 + off);
                uint4 A2 = *(const uint4*)(PR2 + off);
                uint4 C2 = *(const uint4*)(PC2 + off);
                uint32_t a1u[4] = {A1.x, A1.y, A1.z, A1.w};
                uint32_t c1u[4] = {C1.x, C1.y, C1.z, C1.w};
                uint32_t a2u[4] = {A2.x, A2.y, A2.z, A2.w};
                uint32_t c2u[4] = {C2.x, C2.y, C2.z, C2.w};
                #pragma unroll
                for (int q = 0; q < 4; q++) {
                    const int nn = 4 * P + q;
                    float2 p1 = h2f(a1u[q]);
                    float2 q1 = h2f(c1u[q]);
                    float2 p2 = h2f(a2u[q]);
                    float2 q2 = h2f(c2u[q]);
                    acc[nn][0] = RELU_RNA(acc[nn][0] + p1.x + q1.x);
                    acc[nn][1] = RELU_RNA(acc[nn][1] + p1.y + q1.y);
                    acc[nn][2] = RELU_RNA(acc[nn][2] + p2.x + q2.x);
                    acc[nn][3] = RELU_RNA(acc[nn][3] + p2.y + q2.y);
                }
            }
        }

        // quad-shuffle transpose -> layer-2 A fragments
        #pragma unroll
        for (int kk = 0; kk < 16; kk++) {
            float t0 = __shfl_sync(0xffffffffu, acc[kk][0], s0, 4);
            float t1 = __shfl_sync(0xffffffffu, acc[kk][1], s0, 4);
            float t2 = __shfl_sync(0xffffffffu, acc[kk][2], s0, 4);
            float t3 = __shfl_sync(0xffffffffu, acc[kk][3], s0, 4);
            float u0 = __shfl_sync(0xffffffffu, acc[kk][0], s1, 4);
            float u1 = __shfl_sync(0xffffffffu, acc[kk][1], s1, 4);
            float u2 = __shfl_sync(0xffffffffu, acc[kk][2], s1, 4);
            float u3 = __shfl_sync(0xffffffffu, acc[kk][3], s1, 4);
            acc[kk][0] = sel ? t1 : t0;
            acc[kk][1] = sel ? t3 : t2;
            acc[kk][2] = sel ? u1 : u0;
            acc[kk][3] = sel ? u3 : u2;
        }

        // layer-2 mma
        float acc2[8][4];
        #pragma unroll
        for (int nn = 0; nn < 8; nn++) {
            acc2[nn][0] = acc2[nn][1] = acc2[nn][2] = acc2[nn][3] = 0.f;
        }
        #pragma unroll
        for (int kk = 0; kk < 16; kk++) {
            uint32_t a[4];
            a[0] = __float_as_uint(acc[kk][0]);
            a[1] = __float_as_uint(acc[kk][1]);
            a[2] = __float_as_uint(acc[kk][2]);
            a[3] = __float_as_uint(acc[kk][3]);
            #pragma unroll
            for (int nn = 0; nn < 8; nn++) {
                uint32_t b[2];
                const uint2 bv = *(const uint2*)&smu[S_B2 + (kk * 8 + nn) * 66 + lane * 2];
                b[0] = bv.x; b[1] = bv.y;
                mma_tf32(acc2[nn], a, b);
            }
        }

        // output: lane-pair exchange -> float4 stores + red.v4
        {
            const int row  = even ? r1 : r2;
            const int ced  = even ? ce1 : ce2;
            float* op = out_edge + (size_t)(e0 + row) * 64;
            float* mp = g_msg + (size_t)ced * 64;
            #pragma unroll
            for (int nn = 0; nn < 8; nn++) {
                float sa = __shfl_xor_sync(0xffffffffu, acc2[nn][0], 1);
                float sb = __shfl_xor_sync(0xffffffffu, acc2[nn][1], 1);
                float sc = __shfl_xor_sync(0xffffffffu, acc2[nn][2], 1);
                float sd = __shfl_xor_sync(0xffffffffu, acc2[nn][3], 1);
                int base = nn * 8 + qb;
                float4 bb = *(const float4*)&sm[S_EB2 + base];
                float4 o;
                if (even) {
                    o = make_float4(acc2[nn][0] + bb.x, acc2[nn][1] + bb.y,
                                    sa + bb.z, sb + bb.w);
                } else {
                    o = make_float4(sc + bb.x, sd + bb.y,
                                    acc2[nn][2] + bb.z, acc2[nn][3] + bb.w);
                }
                *(float4*)(op + base) = o;
                asm volatile("red.global.add.v4.f32 [%0], {%1,%2,%3,%4};"
                             :: "l"(mp + base), "f"(o.x), "f"(o.y), "f"(o.z), "f"(o.w)
                             : "memory");
            }
        }

        CP_WAIT0();
        __syncwarp();
    }
}

// ---------------------------------------------------------------------------
// Node kernel — same skeleton; fp16 uint4 PX gathers; no atomics.
// ---------------------------------------------------------------------------
__global__ void __launch_bounds__(256, 2) node_kernel(
    const float* __restrict__ nW1,
    const float* __restrict__ nW2, const float* __restrict__ nb2,
    float* __restrict__ out_node)
{
    extern __shared__ float sm[];
    uint32_t* smu = reinterpret_cast<uint32_t*>(sm);
    const uint32_t sbase = smem_u32(sm);

    const int tid  = threadIdx.x;
    const int lane = tid & 31;
    const int w    = tid >> 5;
    const int gr   = lane >> 2;
    const int ct   = lane & 3;
    const int s0   = ct >> 1;
    const int s1   = 2 + (ct >> 1);
    const int sel  = ct & 1;
    const int even = (ct & 1) == 0;
    const int qb   = 4 * (ct >> 1);
    const int r1   = 16 * w + gr;
    const int r2   = r1 + 8;

    const uint32_t slabBase = sbase + (S_A + 16 * w * 68) * 4;

    // ---- prologue ----
    for (int t = tid; t < 2048; t += 256) {
        int k = t >> 5, n4 = (t & 31) << 2;
        float4 v = *(const float4*)&nW1[(64 + k) * 128 + n4];
        int pane = (k >> 3) * 16 + (n4 >> 3);
        int j    = (k >> 2) & 1;
        int ln0  = ((n4 & 7) << 2) | (k & 3);
        uint32_t* p = &smu[S_B1 + pane * 66 + j];
        p[(ln0 + 0)  * 2] = f32_to_tf32(v.x);
        p[(ln0 + 4)  * 2] = f32_to_tf32(v.y);
        p[(ln0 + 8)  * 2] = f32_to_tf32(v.z);
        p[(ln0 + 12) * 2] = f32_to_tf32(v.w);
    }
    for (int t = tid; t < 2048; t += 256) {
        int k = t >> 4, n4 = (t & 15) << 2;
        float4 v = *(const float4*)&nW2[k * 64 + n4];
        int pane = (k >> 3) * 8 + (n4 >> 3);
        int j    = (k >> 2) & 1;
        int ln0  = ((n4 & 7) << 2) | (k & 3);
        uint32_t* p = &smu[S_B2 + pane * 66 + j];
        p[(ln0 + 0)  * 2] = f32_to_tf32(v.x);
        p[(ln0 + 4)  * 2] = f32_to_tf32(v.y);
        p[(ln0 + 8)  * 2] = f32_to_tf32(v.z);
        p[(ln0 + 12) * 2] = f32_to_tf32(v.w);
    }
    if (tid < 64) sm[S_EB2 + tid] = nb2[tid];

    {
        int n0 = blockIdx.x * 128;
        #pragma unroll
        for (int i = 0; i < 8; i++) {
            int idx = lane + 32 * i;
            int rl = idx >> 4, c4 = (idx & 15) << 2;
            int row = n0 + 16 * w + rl;
            uint32_t nbytes = (row < NN) ? 16u : 0u;
            const float* src = g_msg + (size_t)min(row, NN - 1) * 64 + c4;
            CP_ASYNC16_Z(slabBase + (rl * 68 + c4) * 4, src, nbytes);
        }
        CP_COMMIT();
    }
    __syncthreads();
    CP_WAIT0();
    __syncwarp();

    for (int tile = blockIdx.x; tile < NTILN; tile += PGRID) {
        const int n0 = tile * 128;

        float acc[16][4];
        #pragma unroll
        for (int nn = 0; nn < 16; nn++) {
            acc[nn][0] = acc[nn][1] = acc[nn][2] = acc[nn][3] = 0.f;
        }
        #pragma unroll
        for (int kk = 0; kk < 8; kk++) {
            const int col = kk * 8 + ct;
            uint32_t a[4];
            a[0] = smu[S_A + r1 * 68 + col];
            a[1] = smu[S_A + r2 * 68 + col];
            a[2] = smu[S_A + r1 * 68 + col + 4];
            a[3] = smu[S_A + r2 * 68 + col + 4];
            #pragma unroll
            for (int nn = 0; nn < 16; nn++) {
                uint32_t b[2];
                const uint2 bv = *(const uint2*)&smu[S_B1 + (kk * 16 + nn) * 66 + lane * 2];
                b[0] = bv.x; b[1] = bv.y;
                mma_tf32(acc[nn], a, b);
            }
        }
        __syncwarp();

        {
            int ntile = tile + PGRID;
            if (ntile < NTILN) {
                int nn0 = ntile * 128;
                #pragma unroll
                for (int i = 0; i < 8; i++) {
                    int idx = lane + 32 * i;
                    int rl = idx >> 4, c4 = (idx & 15) << 2;
                    int row = nn0 + 16 * w + rl;
                    uint32_t nbytes = (row < NN) ? 16u : 0u;
                    const float* src = g_msg + (size_t)min(row, NN - 1) * 64 + c4;
                    CP_ASYNC16_Z(slabBase + (rl * 68 + c4) * 4, src, nbytes);
                }
            }
            CP_COMMIT();
        }

        // epilogue: fp16 uint4 PX gathers (nb1 already folded)
        {
            const __half* PX1 = g_PX + (size_t)min(n0 + r1, NN - 1) * 128;
            const __half* PX2 = g_PX + (size_t)min(n0 + r2, NN - 1) * 128;
            #pragma unroll
            for (int P = 0; P < 4; P++) {
                const int off = 32 * P + 8 * ct;
                uint4 A1 = *(const uint4*)(PX1 + off);
                uint4 A2 = *(const uint4*)(PX2 + off);
                uint32_t a1u[4] = {A1.x, A1.y, A1.z, A1.w};
                uint32_t a2u[4] = {A2.x, A2.y, A2.z, A2.w};
                #pragma unroll
                for (int q = 0; q < 4; q++) {
                    const int nn = 4 * P + q;
                    float2 p1 = h2f(a1u[q]);
                    float2 p2 = h2f(a2u[q]);
                    acc[nn][0] = RELU_RNA(acc[nn][0] + p1.x);
                    acc[nn][1] = RELU_RNA(acc[nn][1] + p1.y);
                    acc[nn][2] = RELU_RNA(acc[nn][2] + p2.x);
                    acc[nn][3] = RELU_RNA(acc[nn][3] + p2.y);
                }
            }
        }

        #pragma unroll
        for (int kk = 0; kk < 16; kk++) {
            float t0 = __shfl_sync(0xffffffffu, acc[kk][0], s0, 4);
            float t1 = __shfl_sync(0xffffffffu, acc[kk][1], s0, 4);
            float t2 = __shfl_sync(0xffffffffu, acc[kk][2], s0, 4);
            float t3 = __shfl_sync(0xffffffffu, acc[kk][3], s0, 4);
            float u0 = __shfl_sync(0xffffffffu, acc[kk][0], s1, 4);
            float u1 = __shfl_sync(0xffffffffu, acc[kk][1], s1, 4);
            float u2 = __shfl_sync(0xffffffffu, acc[kk][2], s1, 4);
            float u3 = __shfl_sync(0xffffffffu, acc[kk][3], s1, 4);
            acc[kk][0] = sel ? t1 : t0;
            acc[kk][1] = sel ? t3 : t2;
            acc[kk][2] = sel ? u1 : u0;
            acc[kk][3] = sel ? u3 : u2;
        }

        float acc2[8][4];
        #pragma unroll
        for (int nn = 0; nn < 8; nn++) {
            acc2[nn][0] = acc2[nn][1] = acc2[nn][2] = acc2[nn][3] = 0.f;
        }
        #pragma unroll
        for (int kk = 0; kk < 16; kk++) {
            uint32_t a[4];
            a[0] = __float_as_uint(acc[kk][0]);
            a[1] = __float_as_uint(acc[kk][1]);
            a[2] = __float_as_uint(acc[kk][2]);
            a[3] = __float_as_uint(acc[kk][3]);
            #pragma unroll
            for (int nn = 0; nn < 8; nn++) {
                uint32_t b[2];
                const uint2 bv = *(const uint2*)&smu[S_B2 + (kk * 8 + nn) * 66 + lane * 2];
                b[0] = bv.x; b[1] = bv.y;
                mma_tf32(acc2[nn], a, b);
            }
        }

        {
            const int row = even ? r1 : r2;
            const int n   = n0 + row;
            float* op = out_node + (size_t)n * 64;
            #pragma unroll
            for (int nn = 0; nn < 8; nn++) {
                float sa = __shfl_xor_sync(0xffffffffu, acc2[nn][0], 1);
                float sb = __shfl_xor_sync(0xffffffffu, acc2[nn][1], 1);
                float sc = __shfl_xor_sync(0xffffffffu, acc2[nn][2], 1);
                float sd = __shfl_xor_sync(0xffffffffu, acc2[nn][3], 1);
                int base = nn * 8 + qb;
                float4 bb = *(const float4*)&sm[S_EB2 + base];
                float4 o;
                if (even) {
                    o = make_float4(acc2[nn][0] + bb.x, acc2[nn][1] + bb.y,
                                    sa + bb.z, sb + bb.w);
                } else {
                    o = make_float4(sc + bb.x, sd + bb.y,
                                    acc2[nn][2] + bb.z, acc2[nn][3] + bb.w);
                }
                if (n < NN) *(float4*)(op + base) = o;
            }
        }

        CP_WAIT0();
        __syncwarp();
    }
}

// ---------------------------------------------------------------------------
extern "C" void kernel_launch(void* const* d_in, const int* in_sizes, int n_in,
                              void* d_out, int out_size)
{
    const float* x    = (const float*)d_in[0];
    const int*   ei   = (const int*)  d_in[1];
    const float* ea   = (const float*)d_in[2];
    const float* eW1  = (const float*)d_in[3];
    const float* eb1  = (const float*)d_in[4];
    const float* eW2  = (const float*)d_in[5];
    const float* eb2  = (const float*)d_in[6];
    const float* nW1  = (const float*)d_in[7];
    const float* nb1  = (const float*)d_in[8];
    const float* nW2  = (const float*)d_in[9];
    const float* nb2  = (const float*)d_in[10];

    float* out_node = (float*)d_out;             // [NN, 64]
    float* out_edge = (float*)d_out + NN * ND;   // [NE, 64]

    const int smem_pre = (64 * 68 + 64 * 256) * 4;   // 82944
    const int smem_px  = (64 * 68 + 64 * 128) * 4;   // 50176

    cudaFuncSetAttribute(precompute_kernel,
        cudaFuncAttributeMaxDynamicSharedMemorySize, smem_pre);
    cudaFuncSetAttribute(precompute_px_kernel,
        cudaFuncAttributeMaxDynamicSharedMemorySize, smem_px);
    cudaFuncSetAttribute(edge_kernel,
        cudaFuncAttributeMaxDynamicSharedMemorySize, MMA_SMEM_BYTES);
    cudaFuncSetAttribute(node_kernel,
        cudaFuncAttributeMaxDynamicSharedMemorySize, MMA_SMEM_BYTES);

    zero_msg_kernel<<<(NN * ED / 4) / 256, 256>>>();
    precompute_kernel<<<(NN + 63) / 64, 256, smem_pre>>>(x, eW1, eb1);
    precompute_px_kernel<<<(NN + 63) / 64, 256, smem_px>>>(x, nW1, nb1);
    edge_kernel<<<PGRID, 256, MMA_SMEM_BYTES>>>(ea, ei, eW1, eW2, eb2, out_edge);
    node_kernel<<<PGRID, 256, MMA_SMEM_BYTES>>>(nW1, nW2, nb2, out_node);
}

// round 17
// speedup vs baseline: 1.2555x; 1.0438x over previous
#include <cuda_runtime.h>
#include <cuda_fp16.h>
#include <cstdint>

// Problem constants
constexpr int NN  = 50000;   // nodes
constexpr int NE  = 800000;  // edges
constexpr int ND  = 64;      // node dim
constexpr int ED  = 64;      // edge dim
constexpr int HID = 128;     // hidden

constexpr int NTILES = NE / 128;            // 6250 edge tiles
constexpr int NTILN  = (NN + 127) / 128;    // 391 node tiles
constexpr int PGRID  = 296;                 // 2 CTAs x 148 SMs, persistent

// Scratch (device globals: allocation-free)
// Tables are fp16, hidden dim permuted by hperm16 (pair-packed for uint4
// gathers), with eb1 folded into PR and nb1 folded into PX.
__device__ __half g_PR[NN * HID];   // perm16(x @ eW1[64:128] + eb1)
__device__ __half g_PC[NN * HID];   // perm16(x @ eW1[128:192])
__device__ __half g_PX[NN * HID];   // perm16(x @ nW1[0:64] + nb1)
__device__ float  g_msg[NN * ED];   // scatter-add accumulator (fp32)

// fp16 table permutation: mma hidden position m -> physical half offset.
__host__ __device__ __forceinline__ int hperm16(int m) {
    return 32 * (m >> 5) + 8 * ((m & 7) >> 1) + 2 * ((m >> 3) & 3) + (m & 1);
}

// ---------------------------------------------------------------------------
// helpers
// ---------------------------------------------------------------------------
__device__ __forceinline__ uint32_t f32_to_tf32(float f) {
    uint32_t u;
    asm("cvt.rna.tf32.f32 %0, %1;" : "=r"(u) : "f"(f));
    return u;
}

__device__ __forceinline__ void mma_tf32(float d[4], const uint32_t a[4],
                                         const uint32_t b[2]) {
    asm volatile(
        "mma.sync.aligned.m16n8k8.row.col.f32.tf32.tf32.f32 "
        "{%0,%1,%2,%3}, {%4,%5,%6,%7}, {%8,%9}, {%0,%1,%2,%3};"
        : "+f"(d[0]), "+f"(d[1]), "+f"(d[2]), "+f"(d[3])
        : "r"(a[0]), "r"(a[1]), "r"(a[2]), "r"(a[3]), "r"(b[0]), "r"(b[1]));
}

__device__ __forceinline__ uint32_t smem_u32(const void* p) {
    uint32_t a;
    asm("{ .reg .u64 t; cvta.to.shared.u64 t, %1; cvt.u32.u64 %0, t; }"
        : "=r"(a) : "l"(p));
    return a;
}

__device__ __forceinline__ float2 h2f(uint32_t u) {
    __half2 h = *reinterpret_cast<__half2*>(&u);
    return __half22float2(h);
}

#define CP_ASYNC16(dst_u32, src_ptr) \
    asm volatile("cp.async.cg.shared.global [%0], [%1], 16;" \
                 :: "r"(dst_u32), "l"(src_ptr))
#define CP_ASYNC16_Z(dst_u32, src_ptr, src_bytes) \
    asm volatile("cp.async.cg.shared.global [%0], [%1], 16, %2;" \
                 :: "r"(dst_u32), "l"(src_ptr), "r"(src_bytes))
#define CP_COMMIT()  asm volatile("cp.async.commit_group;")
#define CP_WAIT0()   asm volatile("cp.async.wait_group 0;" ::: "memory")

#define RELU_RNA(x) __uint_as_float(f32_to_tf32(fmaxf((x), 0.f)))

// ---------------------------------------------------------------------------
__global__ void zero_msg_kernel() {
    int i = blockIdx.x * blockDim.x + threadIdx.x;
    reinterpret_cast<float4*>(g_msg)[i] = make_float4(0.f, 0.f, 0.f, 0.f);
}

// ---------------------------------------------------------------------------
// Precompute PR/PC (fp16 tables, permuted, eb1 folded into PR):
// GEMM [NN,64] @ [64,256]
// ---------------------------------------------------------------------------
__global__ void __launch_bounds__(256, 2) precompute_kernel(
    const float* __restrict__ x, const float* __restrict__ eW1,
    const float* __restrict__ eb1)
{
    extern __shared__ float sm[];
    float* Xs = sm;               // [64][68]
    float* Ws = sm + 64 * 68;     // [64][256]

    const int n0 = blockIdx.x * 64;
    const int tid = threadIdx.x;

    for (int idx = tid; idx < 64 * 64; idx += 256) {
        int r = idx >> 6, c = idx & 63;
        int n = n0 + r;
        Xs[r * 68 + c] = (n < NN) ? x[n * 64 + c] : 0.f;
    }
    for (int idx = tid; idx < 64 * 256; idx += 256) {
        int k = idx >> 8, j = idx & 255;
        float v = (j < 128) ? eW1[(64 + k) * 128 + j]
                            : eW1[(128 + k) * 128 + (j - 128)];
        Ws[k * 256 + j] = v;
    }
    __syncthreads();

    const int tx = tid & 15;
    const int ty = tid >> 4;

    float acc[4][16];
    #pragma unroll
    for (int i = 0; i < 4; i++)
        #pragma unroll
        for (int j = 0; j < 16; j++) acc[i][j] = 0.f;

    #pragma unroll 4
    for (int k = 0; k < 64; k++) {
        float a[4];
        #pragma unroll
        for (int i = 0; i < 4; i++) a[i] = Xs[(ty * 4 + i) * 68 + k];
        const float4 b0 = *(const float4*)&Ws[k * 256 + tx * 16 + 0];
        const float4 b1 = *(const float4*)&Ws[k * 256 + tx * 16 + 4];
        const float4 b2 = *(const float4*)&Ws[k * 256 + tx * 16 + 8];
        const float4 b3 = *(const float4*)&Ws[k * 256 + tx * 16 + 12];
        float b[16] = {b0.x, b0.y, b0.z, b0.w, b1.x, b1.y, b1.z, b1.w,
                       b2.x, b2.y, b2.z, b2.w, b3.x, b3.y, b3.z, b3.w};
        #pragma unroll
        for (int i = 0; i < 4; i++)
            #pragma unroll
            for (int j = 0; j < 16; j++)
                acc[i][j] = fmaf(a[i], b[j], acc[i][j]);
    }

    const bool isPR = (tx < 8);
    __half* dst = isPR ? g_PR : g_PC;
    int     cb  = isPR ? tx * 16 : (tx - 8) * 16;
    #pragma unroll
    for (int i = 0; i < 4; i++) {
        int n = n0 + ty * 4 + i;
        if (n >= NN) continue;
        #pragma unroll
        for (int jj = 0; jj < 16; jj++) {
            int m = cb + jj;
            float v = acc[i][jj] + (isPR ? eb1[m] : 0.f);
            dst[(size_t)n * 128 + hperm16(m)] = __float2half_rn(v);
        }
    }
}

// ---------------------------------------------------------------------------
// Precompute PX (fp16, permuted, nb1 folded): PX = x @ nW1[0:64]
// ---------------------------------------------------------------------------
__global__ void __launch_bounds__(256, 2) precompute_px_kernel(
    const float* __restrict__ x, const float* __restrict__ nW1,
    const float* __restrict__ nb1)
{
    extern __shared__ float sm[];
    float* Xs = sm;               // [64][68]
    float* Ws = sm + 64 * 68;     // [64][128]

    const int n0 = blockIdx.x * 64;
    const int tid = threadIdx.x;

    for (int idx = tid; idx < 64 * 64; idx += 256) {
        int r = idx >> 6, c = idx & 63;
        int n = n0 + r;
        Xs[r * 68 + c] = (n < NN) ? x[n * 64 + c] : 0.f;
    }
    for (int idx = tid; idx < 64 * 128; idx += 256)
        Ws[idx] = nW1[idx];
    __syncthreads();

    const int tx = tid & 15;
    const int ty = tid >> 4;

    float acc[4][8];
    #pragma unroll
    for (int i = 0; i < 4; i++)
        #pragma unroll
        for (int j = 0; j < 8; j++) acc[i][j] = 0.f;

    #pragma unroll 4
    for (int k = 0; k < 64; k++) {
        float a[4];
        #pragma unroll
        for (int i = 0; i < 4; i++) a[i] = Xs[(ty * 4 + i) * 68 + k];
        const float4 b0 = *(const float4*)&Ws[k * 128 + tx * 8 + 0];
        const float4 b1 = *(const float4*)&Ws[k * 128 + tx * 8 + 4];
        float b[8] = {b0.x, b0.y, b0.z, b0.w, b1.x, b1.y, b1.z, b1.w};
        #pragma unroll
        for (int i = 0; i < 4; i++)
            #pragma unroll
            for (int j = 0; j < 8; j++)
                acc[i][j] = fmaf(a[i], b[j], acc[i][j]);
    }

    #pragma unroll
    for (int i = 0; i < 4; i++) {
        int n = n0 + ty * 4 + i;
        if (n >= NN) continue;
        #pragma unroll
        for (int jj = 0; jj < 8; jj++) {
            int m = tx * 8 + jj;
            g_PX[(size_t)n * 128 + hperm16(m)] =
                __float2half_rn(acc[i][jj] + nb1[m]);
        }
    }
}

// ---------------------------------------------------------------------------
// Smem layout for persistent mma kernels (68864 B, 2 CTAs/SM)
// B fragments stored as packed half2: one uint32 per (pane, lane);
// pane stride 33 words (conflict-free: bank = (pane + lane) & 31).
// ---------------------------------------------------------------------------
constexpr int S_A   = 0;          // A [128][68] fp32 (8704 words)
constexpr int S_B1  = 8704;       // B1frag half2 [pane=kk*16+nn][33]
constexpr int S_B2  = 12928;      // B2frag half2 [pane=kk*8+nn][33]
constexpr int S_EB2 = 17152;      // bias2 [64] fp32
constexpr int MMA_SMEM_BYTES = 17216 * 4;   // 68864

// ---------------------------------------------------------------------------
// Edge kernel — persistent, barrier-free main loop, per-warp A slabs,
// fp16 uint4 gathers + fp16-packed B fragments (1-wavefront b-loads).
// ---------------------------------------------------------------------------
__global__ void __launch_bounds__(256, 2) edge_kernel(
    const float* __restrict__ edge_attr,
    const int*   __restrict__ edge_index,   // [2][NE]
    const float* __restrict__ eW1,
    const float* __restrict__ eW2,
    const float* __restrict__ eb2,
    float* __restrict__ out_edge)
{
    extern __shared__ float sm[];
    uint32_t* smu = reinterpret_cast<uint32_t*>(sm);
    __half*   smh = reinterpret_cast<__half*>(sm);
    const uint32_t sbase = smem_u32(sm);

    const int tid  = threadIdx.x;
    const int lane = tid & 31;
    const int w    = tid >> 5;
    const int gr   = lane >> 2;
    const int ct   = lane & 3;
    const int s0   = ct >> 1;
    const int s1   = 2 + (ct >> 1);
    const int sel  = ct & 1;
    const int even = (ct & 1) == 0;
    const int qb   = 4 * (ct >> 1);
    const int r1   = 16 * w + gr;
    const int r2   = r1 + 8;

    const uint32_t slabBase = sbase + (S_A + 16 * w * 68) * 4;

    // ---- prologue: fp16-packed B fragments + eb2 (once) ----
    // B1: frag (kk,nn,lane): k0 = kk*8+(ln&3), k1 = k0+4, n = nn*8+(ln>>2)
    for (int t = tid; t < 2048; t += 256) {
        int k = t >> 5, n4 = (t & 31) << 2;
        float4 v = *(const float4*)&eW1[k * 128 + n4];
        int pane = (k >> 3) * 16 + (n4 >> 3);
        int j    = (k >> 2) & 1;                 // lo/hi half of pair
        int ln0  = ((n4 & 7) << 2) | (k & 3);
        __half* p = &smh[(S_B1 + pane * 33) * 2 + j];
        p[(ln0 + 0)  * 2] = __float2half_rn(v.x);
        p[(ln0 + 4)  * 2] = __float2half_rn(v.y);
        p[(ln0 + 8)  * 2] = __float2half_rn(v.z);
        p[(ln0 + 12) * 2] = __float2half_rn(v.w);
    }
    for (int t = tid; t < 2048; t += 256) {
        int k = t >> 4, n4 = (t & 15) << 2;
        float4 v = *(const float4*)&eW2[k * 64 + n4];
        int pane = (k >> 3) * 8 + (n4 >> 3);
        int j    = (k >> 2) & 1;
        int ln0  = ((n4 & 7) << 2) | (k & 3);
        __half* p = &smh[(S_B2 + pane * 33) * 2 + j];
        p[(ln0 + 0)  * 2] = __float2half_rn(v.x);
        p[(ln0 + 4)  * 2] = __float2half_rn(v.y);
        p[(ln0 + 8)  * 2] = __float2half_rn(v.z);
        p[(ln0 + 12) * 2] = __float2half_rn(v.w);
    }
    if (tid < 64) sm[S_EB2 + tid] = eb2[tid];

    // ---- per-warp A slab for first tile ----
    {
        int e0 = blockIdx.x * 128;
        #pragma unroll
        for (int i = 0; i < 8; i++) {
            int idx = lane + 32 * i;
            int rl = idx >> 4, c4 = (idx & 15) << 2;
            CP_ASYNC16(slabBase + (rl * 68 + c4) * 4,
                       edge_attr + (size_t)(e0 + 16 * w + rl) * 64 + c4);
        }
        CP_COMMIT();
    }
    __syncthreads();   // B fragments visible; the ONLY block barrier
    CP_WAIT0();
    __syncwarp();

    // ---- persistent tile loop (no block barriers) ----
    for (int tile = blockIdx.x; tile < NTILES; tile += PGRID) {
        const int e0 = tile * 128;

        const int re1 = __ldg(&edge_index[e0 + r1]);
        const int re2 = __ldg(&edge_index[e0 + r2]);
        const int ce1 = __ldg(&edge_index[NE + e0 + r1]);
        const int ce2 = __ldg(&edge_index[NE + e0 + r2]);

        // layer-1 mma (A from own slab, fp16-packed B)
        float acc[16][4];
        #pragma unroll
        for (int nn = 0; nn < 16; nn++) {
            acc[nn][0] = acc[nn][1] = acc[nn][2] = acc[nn][3] = 0.f;
        }
        #pragma unroll
        for (int kk = 0; kk < 8; kk++) {
            const int col = kk * 8 + ct;
            uint32_t a[4];
            a[0] = smu[S_A + r1 * 68 + col];
            a[1] = smu[S_A + r2 * 68 + col];
            a[2] = smu[S_A + r1 * 68 + col + 4];
            a[3] = smu[S_A + r2 * 68 + col + 4];
            #pragma unroll
            for (int nn = 0; nn < 16; nn++) {
                float2 bf = h2f(smu[S_B1 + (kk * 16 + nn) * 33 + lane]);
                uint32_t b[2];
                b[0] = __float_as_uint(bf.x);
                b[1] = __float_as_uint(bf.y);
                mma_tf32(acc[nn], a, b);
            }
        }
        __syncwarp();   // all lanes done reading this warp's slab

        // per-warp prefetch of next tile's slab
        {
            int ntile = tile + PGRID;
            if (ntile < NTILES) {
                int ne0 = ntile * 128;
                #pragma unroll
                for (int i = 0; i < 8; i++) {
                    int idx = lane + 32 * i;
                    int rl = idx >> 4, c4 = (idx & 15) << 2;
                    CP_ASYNC16(slabBase + (rl * 68 + c4) * 4,
                               edge_attr + (size_t)(ne0 + 16 * w + rl) * 64 + c4);
                }
            }
            CP_COMMIT();
        }

        // ---- epilogue: fp16 uint4 gathers, 4 P-groups of 4 octets ----
        {
            const __half* PR1 = g_PR + (size_t)re1 * 128;
            const __half* PR2 = g_PR + (size_t)re2 * 128;
            const __half* PC1 = g_PC + (size_t)ce1 * 128;
            const __half* PC2 = g_PC + (size_t)ce2 * 128;
            #pragma unroll
            for (int P = 0; P < 4; P++) {
                const int off = 32 * P + 8 * ct;   // halfs
                uint4 A1 = *(const uint4*)(PR1 + off);
                uint4 C1 = *(const uint4*)(PC1 + off);
                uint4 A2 = *(const uint4*)(PR2 + off);
                uint4 C2 = *(const uint4*)(PC2 + off);
                uint32_t a1u[4] = {A1.x, A1.y, A1.z, A1.w};
                uint32_t c1u[4] = {C1.x, C1.y, C1.z, C1.w};
                uint32_t a2u[4] = {A2.x, A2.y, A2.z, A2.w};
                uint32_t c2u[4] = {C2.x, C2.y, C2.z, C2.w};
                #pragma unroll
                for (int q = 0; q < 4; q++) {
                    const int nn = 4 * P + q;
                    float2 p1 = h2f(a1u[q]);
                    float2 q1 = h2f(c1u[q]);
                    float2 p2 = h2f(a2u[q]);
                    float2 q2 = h2f(c2u[q]);
                    acc[nn][0] = RELU_RNA(acc[nn][0] + p1.x + q1.x);
                    acc[nn][1] = RELU_RNA(acc[nn][1] + p1.y + q1.y);
                    acc[nn][2] = RELU_RNA(acc[nn][2] + p2.x + q2.x);
                    acc[nn][3] = RELU_RNA(acc[nn][3] + p2.y + q2.y);
                }
            }
        }

        // quad-shuffle transpose -> layer-2 A fragments
        #pragma unroll
        for (int kk = 0; kk < 16; kk++) {
            float t0 = __shfl_sync(0xffffffffu, acc[kk][0], s0, 4);
            float t1 = __shfl_sync(0xffffffffu, acc[kk][1], s0, 4);
            float t2 = __shfl_sync(0xffffffffu, acc[kk][2], s0, 4);
            float t3 = __shfl_sync(0xffffffffu, acc[kk][3], s0, 4);
            float u0 = __shfl_sync(0xffffffffu, acc[kk][0], s1, 4);
            float u1 = __shfl_sync(0xffffffffu, acc[kk][1], s1, 4);
            float u2 = __shfl_sync(0xffffffffu, acc[kk][2], s1, 4);
            float u3 = __shfl_sync(0xffffffffu, acc[kk][3], s1, 4);
            acc[kk][0] = sel ? t1 : t0;
            acc[kk][1] = sel ? t3 : t2;
            acc[kk][2] = sel ? u1 : u0;
            acc[kk][3] = sel ? u3 : u2;
        }

        // layer-2 mma (fp16-packed B2)
        float acc2[8][4];
        #pragma unroll
        for (int nn = 0; nn < 8; nn++) {
            acc2[nn][0] = acc2[nn][1] = acc2[nn][2] = acc2[nn][3] = 0.f;
        }
        #pragma unroll
        for (int kk = 0; kk < 16; kk++) {
            uint32_t a[4];
            a[0] = __float_as_uint(acc[kk][0]);
            a[1] = __float_as_uint(acc[kk][1]);
            a[2] = __float_as_uint(acc[kk][2]);
            a[3] = __float_as_uint(acc[kk][3]);
            #pragma unroll
            for (int nn = 0; nn < 8; nn++) {
                float2 bf = h2f(smu[S_B2 + (kk * 8 + nn) * 33 + lane]);
                uint32_t b[2];
                b[0] = __float_as_uint(bf.x);
                b[1] = __float_as_uint(bf.y);
                mma_tf32(acc2[nn], a, b);
            }
        }

        // output: lane-pair exchange -> float4 stores + red.v4
        {
            const int row  = even ? r1 : r2;
            const int ced  = even ? ce1 : ce2;
            float* op = out_edge + (size_t)(e0 + row) * 64;
            float* mp = g_msg + (size_t)ced * 64;
            #pragma unroll
            for (int nn = 0; nn < 8; nn++) {
                float sa = __shfl_xor_sync(0xffffffffu, acc2[nn][0], 1);
                float sb = __shfl_xor_sync(0xffffffffu, acc2[nn][1], 1);
                float sc = __shfl_xor_sync(0xffffffffu, acc2[nn][2], 1);
                float sd = __shfl_xor_sync(0xffffffffu, acc2[nn][3], 1);
                int base = nn * 8 + qb;
                float4 bb = *(const float4*)&sm[S_EB2 + base];
                float4 o;
                if (even) {
                    o = make_float4(acc2[nn][0] + bb.x, acc2[nn][1] + bb.y,
                                    sa + bb.z, sb + bb.w);
                } else {
                    o = make_float4(sc + bb.x, sd + bb.y,
                                    acc2[nn][2] + bb.z, acc2[nn][3] + bb.w);
                }
                *(float4*)(op + base) = o;
                asm volatile("red.global.add.v4.f32 [%0], {%1,%2,%3,%4};"
                             :: "l"(mp + base), "f"(o.x), "f"(o.y), "f"(o.z), "f"(o.w)
                             : "memory");
            }
        }

        CP_WAIT0();
        __syncwarp();
    }
}

// ---------------------------------------------------------------------------
// Node kernel — same skeleton; fp16 gathers + fp16-packed B; no atomics.
// ---------------------------------------------------------------------------
__global__ void __launch_bounds__(256, 2) node_kernel(
    const float* __restrict__ nW1,
    const float* __restrict__ nW2, const float* __restrict__ nb2,
    float* __restrict__ out_node)
{
    extern __shared__ float sm[];
    uint32_t* smu = reinterpret_cast<uint32_t*>(sm);
    __half*   smh = reinterpret_cast<__half*>(sm);
    const uint32_t sbase = smem_u32(sm);

    const int tid  = threadIdx.x;
    const int lane = tid & 31;
    const int w    = tid >> 5;
    const int gr   = lane >> 2;
    const int ct   = lane & 3;
    const int s0   = ct >> 1;
    const int s1   = 2 + (ct >> 1);
    const int sel  = ct & 1;
    const int even = (ct & 1) == 0;
    const int qb   = 4 * (ct >> 1);
    const int r1   = 16 * w + gr;
    const int r2   = r1 + 8;

    const uint32_t slabBase = sbase + (S_A + 16 * w * 68) * 4;

    // ---- prologue ----
    for (int t = tid; t < 2048; t += 256) {
        int k = t >> 5, n4 = (t & 31) << 2;
        float4 v = *(const float4*)&nW1[(64 + k) * 128 + n4];
        int pane = (k >> 3) * 16 + (n4 >> 3);
        int j    = (k >> 2) & 1;
        int ln0  = ((n4 & 7) << 2) | (k & 3);
        __half* p = &smh[(S_B1 + pane * 33) * 2 + j];
        p[(ln0 + 0)  * 2] = __float2half_rn(v.x);
        p[(ln0 + 4)  * 2] = __float2half_rn(v.y);
        p[(ln0 + 8)  * 2] = __float2half_rn(v.z);
        p[(ln0 + 12) * 2] = __float2half_rn(v.w);
    }
    for (int t = tid; t < 2048; t += 256) {
        int k = t >> 4, n4 = (t & 15) << 2;
        float4 v = *(const float4*)&nW2[k * 64 + n4];
        int pane = (k >> 3) * 8 + (n4 >> 3);
        int j    = (k >> 2) & 1;
        int ln0  = ((n4 & 7) << 2) | (k & 3);
        __half* p = &smh[(S_B2 + pane * 33) * 2 + j];
        p[(ln0 + 0)  * 2] = __float2half_rn(v.x);
        p[(ln0 + 4)  * 2] = __float2half_rn(v.y);
        p[(ln0 + 8)  * 2] = __float2half_rn(v.z);
        p[(ln0 + 12) * 2] = __float2half_rn(v.w);
    }
    if (tid < 64) sm[S_EB2 + tid] = nb2[tid];

    {
        int n0 = blockIdx.x * 128;
        #pragma unroll
        for (int i = 0; i < 8; i++) {
            int idx = lane + 32 * i;
            int rl = idx >> 4, c4 = (idx & 15) << 2;
            int row = n0 + 16 * w + rl;
            uint32_t nbytes = (row < NN) ? 16u : 0u;
            const float* src = g_msg + (size_t)min(row, NN - 1) * 64 + c4;
            CP_ASYNC16_Z(slabBase + (rl * 68 + c4) * 4, src, nbytes);
        }
        CP_COMMIT();
    }
    __syncthreads();
    CP_WAIT0();
    __syncwarp();

    for (int tile = blockIdx.x; tile < NTILN; tile += PGRID) {
        const int n0 = tile * 128;

        float acc[16][4];
        #pragma unroll
        for (int nn = 0; nn < 16; nn++) {
            acc[nn][0] = acc[nn][1] = acc[nn][2] = acc[nn][3] = 0.f;
        }
        #pragma unroll
        for (int kk = 0; kk < 8; kk++) {
            const int col = kk * 8 + ct;
            uint32_t a[4];
            a[0] = smu[S_A + r1 * 68 + col];
            a[1] = smu[S_A + r2 * 68 + col];
            a[2] = smu[S_A + r1 * 68 + col + 4];
            a[3] = smu[S_A + r2 * 68 + col + 4];
            #pragma unroll
            for (int nn = 0; nn < 16; nn++) {
                float2 bf = h2f(smu[S_B1 + (kk * 16 + nn) * 33 + lane]);
                uint32_t b[2];
                b[0] = __float_as_uint(bf.x);
                b[1] = __float_as_uint(bf.y);
                mma_tf32(acc[nn], a, b);
            }
        }
        __syncwarp();

        {
            int ntile = tile + PGRID;
            if (ntile < NTILN) {
                int nn0 = ntile * 128;
                #pragma unroll
                for (int i = 0; i < 8; i++) {
                    int idx = lane + 32 * i;
                    int rl = idx >> 4, c4 = (idx & 15) << 2;
                    int row = nn0 + 16 * w + rl;
                    uint32_t nbytes = (row < NN) ? 16u : 0u;
                    const float* src = g_msg + (size_t)min(row, NN - 1) * 64 + c4;
                    CP_ASYNC16_Z(slabBase + (rl * 68 + c4) * 4, src, nbytes);
                }
            }
            CP_COMMIT();
        }

        // epilogue: fp16 uint4 PX gathers (nb1 already folded)
        {
            const __half* PX1 = g_PX + (size_t)min(n0 + r1, NN - 1) * 128;
            const __half* PX2 = g_PX + (size_t)min(n0 + r2, NN - 1) * 128;
            #pragma unroll
            for (int P = 0; P < 4; P++) {
                const int off = 32 * P + 8 * ct;
                uint4 A1 = *(const uint4*)(PX1 + off);
                uint4 A2 = *(const uint4*)(PX2 + off);
                uint32_t a1u[4] = {A1.x, A1.y, A1.z, A1.w};
                uint32_t a2u[4] = {A2.x, A2.y, A2.z, A2.w};
                #pragma unroll
                for (int q = 0; q < 4; q++) {
                    const int nn = 4 * P + q;
                    float2 p1 = h2f(a1u[q]);
                    float2 p2 = h2f(a2u[q]);
                    acc[nn][0] = RELU_RNA(acc[nn][0] + p1.x);
                    acc[nn][1] = RELU_RNA(acc[nn][1] + p1.y);
                    acc[nn][2] = RELU_RNA(acc[nn][2] + p2.x);
                    acc[nn][3] = RELU_RNA(acc[nn][3] + p2.y);
                }
            }
        }

        #pragma unroll
        for (int kk = 0; kk < 16; kk++) {
            float t0 = __shfl_sync(0xffffffffu, acc[kk][0], s0, 4);
            float t1 = __shfl_sync(0xffffffffu, acc[kk][1], s0, 4);
            float t2 = __shfl_sync(0xffffffffu, acc[kk][2], s0, 4);
            float t3 = __shfl_sync(0xffffffffu, acc[kk][3], s0, 4);
            float u0 = __shfl_sync(0xffffffffu, acc[kk][0], s1, 4);
            float u1 = __shfl_sync(0xffffffffu, acc[kk][1], s1, 4);
            float u2 = __shfl_sync(0xffffffffu, acc[kk][2], s1, 4);
            float u3 = __shfl_sync(0xffffffffu, acc[kk][3], s1, 4);
            acc[kk][0] = sel ? t1 : t0;
            acc[kk][1] = sel ? t3 : t2;
            acc[kk][2] = sel ? u1 : u0;
            acc[kk][3] = sel ? u3 : u2;
        }

        float acc2[8][4];
        #pragma unroll
        for (int nn = 0; nn < 8; nn++) {
            acc2[nn][0] = acc2[nn][1] = acc2[nn][2] = acc2[nn][3] = 0.f;
        }
        #pragma unroll
        for (int kk = 0; kk < 16; kk++) {
            uint32_t a[4];
            a[0] = __float_as_uint(acc[kk][0]);
            a[1] = __float_as_uint(acc[kk][1]);
            a[2] = __float_as_uint(acc[kk][2]);
            a[3] = __float_as_uint(acc[kk][3]);
            #pragma unroll
            for (int nn = 0; nn < 8; nn++) {
                float2 bf = h2f(smu[S_B2 + (kk * 8 + nn) * 33 + lane]);
                uint32_t b[2];
                b[0] = __float_as_uint(bf.x);
                b[1] = __float_as_uint(bf.y);
                mma_tf32(acc2[nn], a, b);
            }
        }

        {
            const int row = even ? r1 : r2;
            const int n   = n0 + row;
            float* op = out_node + (size_t)n * 64;
            #pragma unroll
            for (int nn = 0; nn < 8; nn++) {
                float sa = __shfl_xor_sync(0xffffffffu, acc2[nn][0], 1);
                float sb = __shfl_xor_sync(0xffffffffu, acc2[nn][1], 1);
                float sc = __shfl_xor_sync(0xffffffffu, acc2[nn][2], 1);
                float sd = __shfl_xor_sync(0xffffffffu, acc2[nn][3], 1);
                int base = nn * 8 + qb;
                float4 bb = *(const float4*)&sm[S_EB2 + base];
                float4 o;
                if (even) {
                    o = make_float4(acc2[nn][0] + bb.x, acc2[nn][1] + bb.y,
                                    sa + bb.z, sb + bb.w);
                } else {
                    o = make_float4(sc + bb.x, sd + bb.y,
                                    acc2[nn][2] + bb.z, acc2[nn][3] + bb.w);
                }
                if (n < NN) *(float4*)(op + base) = o;
            }
        }

        CP_WAIT0();
        __syncwarp();
    }
}

// ---------------------------------------------------------------------------
extern "C" void kernel_launch(void* const* d_in, const int* in_sizes, int n_in,
                              void* d_out, int out_size)
{
    const float* x    = (const float*)d_in[0];
    const int*   ei   = (const int*)  d_in[1];
    const float* ea   = (const float*)d_in[2];
    const float* eW1  = (const float*)d_in[3];
    const float* eb1  = (const float*)d_in[4];
    const float* eW2  = (const float*)d_in[5];
    const float* eb2  = (const float*)d_in[6];
    const float* nW1  = (const float*)d_in[7];
    const float* nb1  = (const float*)d_in[8];
    const float* nW2  = (const float*)d_in[9];
    const float* nb2  = (const float*)d_in[10];

    float* out_node = (float*)d_out;             // [NN, 64]
    float* out_edge = (float*)d_out + NN * ND;   // [NE, 64]

    const int smem_pre = (64 * 68 + 64 * 256) * 4;   // 82944
    const int smem_px  = (64 * 68 + 64 * 128) * 4;   // 50176

    cudaFuncSetAttribute(precompute_kernel,
        cudaFuncAttributeMaxDynamicSharedMemorySize, smem_pre);
    cudaFuncSetAttribute(precompute_px_kernel,
        cudaFuncAttributeMaxDynamicSharedMemorySize, smem_px);
    cudaFuncSetAttribute(edge_kernel,
        cudaFuncAttributeMaxDynamicSharedMemorySize, MMA_SMEM_BYTES);
    cudaFuncSetAttribute(node_kernel,
        cudaFuncAttributeMaxDynamicSharedMemorySize, MMA_SMEM_BYTES);

    zero_msg_kernel<<<(NN * ED / 4) / 256, 256>>>();
    precompute_kernel<<<(NN + 63) / 64, 256, smem_pre>>>(x, eW1, eb1);
    precompute_px_kernel<<<(NN + 63) / 64, 256, smem_px>>>(x, nW1, nb1);
    edge_kernel<<<PGRID, 256, MMA_SMEM_BYTES>>>(ea, ei, eW1, eW2, eb2, out_edge);
    node_kernel<<<PGRID, 256, MMA_SMEM_BYTES>>>(nW1, nW2, nb2, out_node);
}